// round 2
// baseline (speedup 1.0000x reference)
#include <cuda_runtime.h>
#include <cstdint>

// Problem constants (fixed shapes for this problem)
#define NN 50000        // nodes
#define NE 800000       // edges
#define INC 256
#define HID 128
#define OUTC 1000
#define TDIM 768

// ---------------- scratch (__device__ globals; no allocation allowed) -------
__device__ __align__(256) float g_deg[NN];                 // deg -> deg^-1/2
__device__ __align__(256) float g_h1[(size_t)NN * HID];    // x @ W1
__device__ __align__(256) float g_o1[(size_t)NN * HID];    // conv1 out
__device__ __align__(256) float g_h2[(size_t)NN * HID];    // relu(o1) @ W2
__device__ __align__(256) float g_o2[(size_t)NN * HID];    // conv2 out
__device__ __align__(256) float g_tvec[1024];              // text@Wc[128:]+bc

// ---------------- small kernels --------------------------------------------
__global__ void deg_init(float* deg) {
    int i = blockIdx.x * blockDim.x + threadIdx.x;
    if (i < NN) deg[i] = 1.0f;              // self-loop contributes 1
}

__global__ void deg_count(const int* __restrict__ dst, float* deg) {
    int e = blockIdx.x * blockDim.x + threadIdx.x;
    if (e < NE) atomicAdd(&deg[dst[e]], 1.0f);
}

__global__ void deg_rsqrt(float* deg) {
    int i = blockIdx.x * blockDim.x + threadIdx.x;
    if (i < NN) deg[i] = rsqrtf(deg[i]);    // deg >= 1 always (self-loops)
}

// tvec[o] = bc[o] + sum_d text[d] * Wc[(HID+d)*OUTC + o]   (coalesced over o)
__global__ void text_proj(const float* __restrict__ text,
                          const float* __restrict__ Wc,
                          const float* __restrict__ bc,
                          float* __restrict__ tvec) {
    int o = blockIdx.x * blockDim.x + threadIdx.x;
    if (o >= OUTC) return;
    float s = bc[o];
    #pragma unroll 8
    for (int d = 0; d < TDIM; d++)
        s += text[d] * Wc[(size_t)(HID + d) * OUTC + o];
    tvec[o] = s;
}

// out[i][c] = bias[c] + h[i][c] * dinv[i]^2      (self-loop + bias init)
__global__ void init_self(const float* __restrict__ h,
                          const float* __restrict__ dinv,
                          const float* __restrict__ bias,
                          float* __restrict__ out) {
    int idx = blockIdx.x * blockDim.x + threadIdx.x;
    if (idx >= NN * HID) return;
    int i = idx >> 7;         // /128
    int c = idx & 127;
    float di = dinv[i];
    out[idx] = bias[c] + h[idx] * di * di;
}

// One warp per edge: out[dst] += h[src] * (dinv[src]*dinv[dst])
// 128 floats/row = 32 lanes * float4; vectorized red.global.add.v4.f32
__global__ void scatter_edges(const int* __restrict__ src,
                              const int* __restrict__ dst,
                              const float* __restrict__ dinv,
                              const float* __restrict__ h,
                              float* __restrict__ out) {
    int warp = (blockIdx.x * blockDim.x + threadIdx.x) >> 5;
    int lane = threadIdx.x & 31;
    if (warp >= NE) return;
    int s = src[warp];
    int d = dst[warp];
    float nrm = dinv[s] * dinv[d];
    float4 v = reinterpret_cast<const float4*>(h + (size_t)s * HID)[lane];
    v.x *= nrm; v.y *= nrm; v.z *= nrm; v.w *= nrm;
    float* p = out + (size_t)d * HID + lane * 4;
    asm volatile("red.global.add.v4.f32 [%0], {%1, %2, %3, %4};"
                 :: "l"(p), "f"(v.x), "f"(v.y), "f"(v.z), "f"(v.w)
                 : "memory");
}

// ---------------- fp32 tiled GEMM: C[M,N] = op(A)[M,K] @ B[K,N] (+bias) -----
// BM=BN=128, BK=8, 256 threads, 8x8 per-thread tile. Guards on M and N.
// A row-major lda=K (contiguous), B row-major with explicit ldb.
template<bool RELU_A, bool BIAS>
__global__ void sgemm128(const float* __restrict__ A,
                         const float* __restrict__ B,
                         float* __restrict__ C,
                         const float* __restrict__ bias,
                         int M, int N, int K, int ldb) {
    const int BM = 128, BN = 128, BK = 8, TM = 8, TN = 8;
    __shared__ float As[BK][BM];
    __shared__ float Bs[BK][BN];

    int tid = threadIdx.x;
    int row0 = blockIdx.y * BM;
    int col0 = blockIdx.x * BN;
    int ty = tid / 16, tx = tid % 16;

    float acc[TM][TN];
    #pragma unroll
    for (int m = 0; m < TM; m++)
        #pragma unroll
        for (int n = 0; n < TN; n++) acc[m][n] = 0.f;

    int aRow = tid >> 1;              // 0..127
    int aCol0 = (tid & 1) * 4;        // 0 or 4
    int bRow = tid >> 5;              // 0..7
    int bCol0 = (tid & 31) * 4;       // 0..124

    int gr_a = row0 + aRow;
    bool a_ok = (gr_a < M);
    const float* Arow = A + (size_t)gr_a * K;

    for (int k0 = 0; k0 < K; k0 += BK) {
        #pragma unroll
        for (int j = 0; j < 4; j++) {
            float v = a_ok ? Arow[k0 + aCol0 + j] : 0.f;
            if (RELU_A) v = fmaxf(v, 0.f);
            As[aCol0 + j][aRow] = v;
        }
        const float* Brow = B + (size_t)(k0 + bRow) * ldb;
        #pragma unroll
        for (int j = 0; j < 4; j++) {
            int gc = col0 + bCol0 + j;
            Bs[bRow][bCol0 + j] = (gc < N) ? Brow[gc] : 0.f;
        }
        __syncthreads();

        #pragma unroll
        for (int k = 0; k < BK; k++) {
            float ra[TM], rb[TN];
            #pragma unroll
            for (int m = 0; m < TM; m++) ra[m] = As[k][ty * TM + m];
            #pragma unroll
            for (int n = 0; n < TN; n++) rb[n] = Bs[k][tx * TN + n];
            #pragma unroll
            for (int m = 0; m < TM; m++)
                #pragma unroll
                for (int n = 0; n < TN; n++)
                    acc[m][n] += ra[m] * rb[n];
        }
        __syncthreads();
    }

    #pragma unroll
    for (int m = 0; m < TM; m++) {
        int gr = row0 + ty * TM + m;
        if (gr >= M) continue;
        #pragma unroll
        for (int n = 0; n < TN; n++) {
            int gc = col0 + tx * TN + n;
            if (gc >= N) continue;
            float v = acc[m][n];
            if (BIAS) v += bias[gc];
            C[(size_t)gr * N + gc] = v;
        }
    }
}

// ---------------- launch ----------------------------------------------------
extern "C" void kernel_launch(void* const* d_in, const int* in_sizes, int n_in,
                              void* d_out, int out_size) {
    const float* x    = (const float*)d_in[0];
    const int*   ei   = (const int*)d_in[1];   // JAX downcasts int64->int32
    const float* text = (const float*)d_in[2];
    const float* W1   = (const float*)d_in[3];
    const float* b1   = (const float*)d_in[4];
    const float* W2   = (const float*)d_in[5];
    const float* b2   = (const float*)d_in[6];
    const float* Wc   = (const float*)d_in[7];
    const float* bc   = (const float*)d_in[8];
    float* out = (float*)d_out;

    float *deg, *h1, *o1, *h2, *o2, *tv;
    cudaGetSymbolAddress((void**)&deg, g_deg);
    cudaGetSymbolAddress((void**)&h1,  g_h1);
    cudaGetSymbolAddress((void**)&o1,  g_o1);
    cudaGetSymbolAddress((void**)&h2,  g_h2);
    cudaGetSymbolAddress((void**)&o2,  g_o2);
    cudaGetSymbolAddress((void**)&tv,  g_tvec);

    const int* srcp = ei;        // edge_index[0]
    const int* dstp = ei + NE;   // edge_index[1]

    // degree / normalization
    deg_init <<<(NN + 255) / 256, 256>>>(deg);
    deg_count<<<(NE + 255) / 256, 256>>>(dstp, deg);
    deg_rsqrt<<<(NN + 255) / 256, 256>>>(deg);   // deg now holds deg^-1/2

    // constant text-branch bias vector
    text_proj<<<(OUTC + 255) / 256, 256>>>(text, Wc, bc, tv);

    dim3 gN128((HID + 127) / 128, (NN + 127) / 128);     // (1, 391)
    dim3 gOut((OUTC + 127) / 128, (NN + 127) / 128);     // (8, 391)

    // ---- layer 1: h1 = x @ W1 ; o1 = b1 + self + scatter ----
    sgemm128<false, false><<<gN128, 256>>>(x, W1, h1, nullptr, NN, HID, INC, HID);
    init_self<<<(NN * HID + 255) / 256, 256>>>(h1, deg, b1, o1);
    scatter_edges<<<(NE * 32 + 255) / 256, 256>>>(srcp, dstp, deg, h1, o1);

    // ---- layer 2: h2 = relu(o1) @ W2 ; o2 = b2 + self + scatter ----
    sgemm128<true, false><<<gN128, 256>>>(o1, W2, h2, nullptr, NN, HID, HID, HID);
    init_self<<<(NN * HID + 255) / 256, 256>>>(h2, deg, b2, o2);
    scatter_edges<<<(NE * 32 + 255) / 256, 256>>>(srcp, dstp, deg, h2, o2);

    // ---- classifier: out = o2 @ Wc[:128] + (text @ Wc[128:] + bc) ----
    sgemm128<false, true><<<gOut, 256>>>(o2, Wc, out, tv, NN, OUTC, HID, OUTC);
}

// round 3
// speedup vs baseline: 1.9310x; 1.9310x over previous
#include <cuda_runtime.h>
#include <cstdint>

#define NN 50000
#define NE 800000
#define INC 256
#define HID 128
#define OUTC 1000
#define TDIM 768

// ---------------- scratch ----------------------------------------------------
__device__ __align__(256) float g_deg[NN];
__device__ __align__(256) float g_h1[(size_t)NN * HID];
__device__ __align__(256) float g_o1[(size_t)NN * HID];
__device__ __align__(256) float g_h2[(size_t)NN * HID];
__device__ __align__(256) float g_o2[(size_t)NN * HID];
__device__ __align__(256) float g_tvec[1024];

// ---------------- small kernels ----------------------------------------------
__global__ void deg_init(float* deg) {
    int i = blockIdx.x * blockDim.x + threadIdx.x;
    if (i < NN) deg[i] = 1.0f;
}
__global__ void deg_count(const int* __restrict__ dst, float* deg) {
    int e = blockIdx.x * blockDim.x + threadIdx.x;
    if (e < NE) atomicAdd(&deg[dst[e]], 1.0f);
}
__global__ void deg_rsqrt(float* deg) {
    int i = blockIdx.x * blockDim.x + threadIdx.x;
    if (i < NN) deg[i] = rsqrtf(deg[i]);
}

// tvec init with bc, then split-K partial sums via atomics
__global__ void tvec_init(const float* __restrict__ bc, float* __restrict__ tvec) {
    int o = blockIdx.x * blockDim.x + threadIdx.x;
    if (o < OUTC) tvec[o] = bc[o];
}
// grid: (OUTC/128, TDIM/128); block 128. Each block: 128-length d-chunk partial.
__global__ void text_proj_part(const float* __restrict__ text,
                               const float* __restrict__ Wc,
                               float* __restrict__ tvec) {
    int o = blockIdx.x * 128 + threadIdx.x;
    int d0 = blockIdx.y * 128;
    if (o >= OUTC) return;
    float s = 0.f;
    #pragma unroll 8
    for (int d = d0; d < d0 + 128; d++)
        s += text[d] * Wc[(size_t)(HID + d) * OUTC + o];
    atomicAdd(&tvec[o], s);
}

// out[i][c] = bias[c] + h[i][c] * dinv[i]^2
__global__ void init_self(const float* __restrict__ h,
                          const float* __restrict__ dinv,
                          const float* __restrict__ bias,
                          float* __restrict__ out) {
    int idx = blockIdx.x * blockDim.x + threadIdx.x;
    if (idx >= NN * HID) return;
    int i = idx >> 7;
    int c = idx & 127;
    float di = dinv[i];
    out[idx] = bias[c] + h[idx] * di * di;
}

// warp per edge: out[dst] += h[src] * (dinv[src]*dinv[dst])
__global__ void scatter_edges(const int* __restrict__ src,
                              const int* __restrict__ dst,
                              const float* __restrict__ dinv,
                              const float* __restrict__ h,
                              float* __restrict__ out) {
    int warp = (blockIdx.x * blockDim.x + threadIdx.x) >> 5;
    int lane = threadIdx.x & 31;
    if (warp >= NE) return;
    int s = src[warp];
    int d = dst[warp];
    float nrm = dinv[s] * dinv[d];
    float4 v = reinterpret_cast<const float4*>(h + (size_t)s * HID)[lane];
    v.x *= nrm; v.y *= nrm; v.z *= nrm; v.w *= nrm;
    float* p = out + (size_t)d * HID + lane * 4;
    asm volatile("red.global.add.v4.f32 [%0], {%1, %2, %3, %4};"
                 :: "l"(p), "f"(v.x), "f"(v.y), "f"(v.z), "f"(v.w)
                 : "memory");
}

// ---------------- tf32 tensor-core GEMM --------------------------------------
// C[M,N] = op(A)[M,K] @ B[K,N] (+bias). BM=128, BN=64, BK=32, 256 thr (8 warps).
// Warp grid 4(m) x 2(n); each warp computes 32x32 via m16n8k8 tf32 mma.

__device__ __forceinline__ uint32_t f2tf32(float x) {
    uint32_t u;
    asm("cvt.rna.tf32.f32 %0, %1;" : "=r"(u) : "f"(x));
    return u;
}

__device__ __forceinline__ void mma_tf32(float c[4], uint32_t a0, uint32_t a1,
                                         uint32_t a2, uint32_t a3,
                                         uint32_t b0, uint32_t b1) {
    asm volatile(
        "mma.sync.aligned.m16n8k8.row.col.f32.tf32.tf32.f32 "
        "{%0,%1,%2,%3}, {%4,%5,%6,%7}, {%8,%9}, {%0,%1,%2,%3};"
        : "+f"(c[0]), "+f"(c[1]), "+f"(c[2]), "+f"(c[3])
        : "r"(a0), "r"(a1), "r"(a2), "r"(a3), "r"(b0), "r"(b1));
}

template<bool RELU_A, bool BIAS>
__global__ __launch_bounds__(256)
void tf32gemm(const float* __restrict__ A,
              const float* __restrict__ B,
              float* __restrict__ C,
              const float* __restrict__ bias,
              int M, int N, int K, int ldb) {
    const int BM = 128, BN = 64, BK = 32;
    __shared__ __align__(16) uint32_t As[BM][36];   // [m][k], padded
    __shared__ __align__(16) uint32_t Bs[BK][72];   // [k][n], padded

    int tid  = threadIdx.x;
    int lane = tid & 31;
    int wid  = tid >> 5;
    int gid  = lane >> 2;     // 0..7
    int tig  = lane & 3;      // 0..3
    int wm   = (wid & 3) * 32;  // warp m offset
    int wn   = (wid >> 2) * 32; // warp n offset

    int row0 = blockIdx.y * BM;
    int col0 = blockIdx.x * BN;

    float acc[2][4][4];
    #pragma unroll
    for (int mt = 0; mt < 2; mt++)
        #pragma unroll
        for (int nt = 0; nt < 4; nt++)
            #pragma unroll
            for (int r = 0; r < 4; r++) acc[mt][nt][r] = 0.f;

    for (int k0 = 0; k0 < K; k0 += BK) {
        // load A tile: 128x32 = 1024 float4, 4 per thread
        #pragma unroll
        for (int i = 0; i < 4; i++) {
            int lin = tid + i * 256;          // float4 index
            int row = lin >> 3;               // 8 float4 per row
            int c4  = (lin & 7) * 4;
            int gr  = row0 + row;
            float4 v = make_float4(0.f, 0.f, 0.f, 0.f);
            if (gr < M)
                v = *reinterpret_cast<const float4*>(A + (size_t)gr * K + k0 + c4);
            if (RELU_A) {
                v.x = fmaxf(v.x, 0.f); v.y = fmaxf(v.y, 0.f);
                v.z = fmaxf(v.z, 0.f); v.w = fmaxf(v.w, 0.f);
            }
            As[row][c4 + 0] = f2tf32(v.x);
            As[row][c4 + 1] = f2tf32(v.y);
            As[row][c4 + 2] = f2tf32(v.z);
            As[row][c4 + 3] = f2tf32(v.w);
        }
        // load B tile: 32x64 = 512 float4, 2 per thread
        #pragma unroll
        for (int i = 0; i < 2; i++) {
            int lin = tid + i * 256;
            int row = lin >> 4;               // 16 float4 per row
            int c4  = (lin & 15) * 4;
            int gk  = k0 + row;
            int gc  = col0 + c4;
            float4 v = make_float4(0.f, 0.f, 0.f, 0.f);
            if (gc + 3 < N) {
                v = *reinterpret_cast<const float4*>(B + (size_t)gk * ldb + gc);
            } else if (gc < N) {
                const float* bp = B + (size_t)gk * ldb;
                v.x = bp[gc];
                if (gc + 1 < N) v.y = bp[gc + 1];
                if (gc + 2 < N) v.z = bp[gc + 2];
            }
            Bs[row][c4 + 0] = f2tf32(v.x);
            Bs[row][c4 + 1] = f2tf32(v.y);
            Bs[row][c4 + 2] = f2tf32(v.z);
            Bs[row][c4 + 3] = f2tf32(v.w);
        }
        __syncthreads();

        #pragma unroll
        for (int kc = 0; kc < 4; kc++) {
            int ks = kc * 8;
            uint32_t a[2][4];
            #pragma unroll
            for (int mt = 0; mt < 2; mt++) {
                int r = wm + mt * 16 + gid;
                a[mt][0] = As[r    ][ks + tig];
                a[mt][1] = As[r + 8][ks + tig];
                a[mt][2] = As[r    ][ks + tig + 4];
                a[mt][3] = As[r + 8][ks + tig + 4];
            }
            uint32_t b[4][2];
            #pragma unroll
            for (int nt = 0; nt < 4; nt++) {
                int c = wn + nt * 8 + gid;
                b[nt][0] = Bs[ks + tig    ][c];
                b[nt][1] = Bs[ks + tig + 4][c];
            }
            #pragma unroll
            for (int mt = 0; mt < 2; mt++)
                #pragma unroll
                for (int nt = 0; nt < 4; nt++)
                    mma_tf32(acc[mt][nt], a[mt][0], a[mt][1], a[mt][2], a[mt][3],
                             b[nt][0], b[nt][1]);
        }
        __syncthreads();
    }

    // epilogue
    #pragma unroll
    for (int mt = 0; mt < 2; mt++) {
        #pragma unroll
        for (int rr = 0; rr < 2; rr++) {        // c01 (row+0), c23 (row+8)
            int gr = row0 + wm + mt * 16 + gid + rr * 8;
            if (gr >= M) continue;
            #pragma unroll
            for (int nt = 0; nt < 4; nt++) {
                int gc = col0 + wn + nt * 8 + tig * 2;
                float v0 = acc[mt][nt][rr * 2 + 0];
                float v1 = acc[mt][nt][rr * 2 + 1];
                if (BIAS) {
                    if (gc < N)     v0 += bias[gc];
                    if (gc + 1 < N) v1 += bias[gc + 1];
                }
                float* cp = C + (size_t)gr * N + gc;
                if (gc + 1 < N) {
                    *reinterpret_cast<float2*>(cp) = make_float2(v0, v1);
                } else if (gc < N) {
                    *cp = v0;
                }
            }
        }
    }
}

// ---------------- launch ------------------------------------------------------
extern "C" void kernel_launch(void* const* d_in, const int* in_sizes, int n_in,
                              void* d_out, int out_size) {
    const float* x    = (const float*)d_in[0];
    const int*   ei   = (const int*)d_in[1];
    const float* text = (const float*)d_in[2];
    const float* W1   = (const float*)d_in[3];
    const float* b1   = (const float*)d_in[4];
    const float* W2   = (const float*)d_in[5];
    const float* b2   = (const float*)d_in[6];
    const float* Wc   = (const float*)d_in[7];
    const float* bc   = (const float*)d_in[8];
    float* out = (float*)d_out;

    float *deg, *h1, *o1, *h2, *o2, *tv;
    cudaGetSymbolAddress((void**)&deg, g_deg);
    cudaGetSymbolAddress((void**)&h1,  g_h1);
    cudaGetSymbolAddress((void**)&o1,  g_o1);
    cudaGetSymbolAddress((void**)&h2,  g_h2);
    cudaGetSymbolAddress((void**)&o2,  g_o2);
    cudaGetSymbolAddress((void**)&tv,  g_tvec);

    const int* srcp = ei;
    const int* dstp = ei + NE;

    deg_init <<<(NN + 255) / 256, 256>>>(deg);
    deg_count<<<(NE + 255) / 256, 256>>>(dstp, deg);
    deg_rsqrt<<<(NN + 255) / 256, 256>>>(deg);

    tvec_init<<<(OUTC + 127) / 128, 128>>>(bc, tv);
    dim3 gtp((OUTC + 127) / 128, TDIM / 128);           // (8, 6)
    text_proj_part<<<gtp, 128>>>(text, Wc, tv);

    dim3 gHid((HID + 63) / 64, (NN + 127) / 128);       // (2, 391)
    dim3 gOut((OUTC + 63) / 64, (NN + 127) / 128);      // (16, 391)

    // layer 1
    tf32gemm<false, false><<<gHid, 256>>>(x, W1, h1, nullptr, NN, HID, INC, HID);
    init_self<<<(NN * HID + 255) / 256, 256>>>(h1, deg, b1, o1);
    scatter_edges<<<(NE * 32 + 255) / 256, 256>>>(srcp, dstp, deg, h1, o1);

    // layer 2
    tf32gemm<true, false><<<gHid, 256>>>(o1, W2, h2, nullptr, NN, HID, HID, HID);
    init_self<<<(NN * HID + 255) / 256, 256>>>(h2, deg, b2, o2);
    scatter_edges<<<(NE * 32 + 255) / 256, 256>>>(srcp, dstp, deg, h2, o2);

    // classifier
    tf32gemm<false, true><<<gOut, 256>>>(o2, Wc, out, tv, NN, OUTC, HID, OUTC);
}

// round 5
// speedup vs baseline: 2.5749x; 1.3335x over previous
#include <cuda_runtime.h>
#include <cstdint>

#define NN 50000
#define NE 800000
#define INC 256
#define HID 128
#define OUTC 1000
#define TDIM 768

// ---------------- scratch ----------------------------------------------------
__device__ __align__(256) float g_deg[NN];
__device__ __align__(256) float g_h1[(size_t)NN * HID];
__device__ __align__(256) float g_o1[(size_t)NN * HID];
__device__ __align__(256) float g_h2[(size_t)NN * HID];
__device__ __align__(256) float g_o2[(size_t)NN * HID];
__device__ __align__(256) float g_tvec[1024];

// ---------------- small kernels ----------------------------------------------
__global__ void deg_init(float* deg) {
    int i = blockIdx.x * blockDim.x + threadIdx.x;
    if (i < NN) deg[i] = 1.0f;
}
__global__ void deg_count(const int* __restrict__ dst, float* deg) {
    int e = blockIdx.x * blockDim.x + threadIdx.x;
    if (e < NE) atomicAdd(&deg[dst[e]], 1.0f);
}
__global__ void deg_rsqrt(float* deg) {
    int i = blockIdx.x * blockDim.x + threadIdx.x;
    if (i < NN) deg[i] = rsqrtf(deg[i]);
}

__global__ void tvec_init(const float* __restrict__ bc, float* __restrict__ tvec) {
    int o = blockIdx.x * blockDim.x + threadIdx.x;
    if (o < OUTC) tvec[o] = bc[o];
}
__global__ void text_proj_part(const float* __restrict__ text,
                               const float* __restrict__ Wc,
                               float* __restrict__ tvec) {
    int o = blockIdx.x * 128 + threadIdx.x;
    int d0 = blockIdx.y * 128;
    if (o >= OUTC) return;
    float s = 0.f;
    #pragma unroll 8
    for (int d = d0; d < d0 + 128; d++)
        s += text[d] * Wc[(size_t)(HID + d) * OUTC + o];
    atomicAdd(&tvec[o], s);
}

// warp per edge: out[dst] += h[src] * (dinv[src]*dinv[dst])
__global__ void scatter_edges(const int* __restrict__ src,
                              const int* __restrict__ dst,
                              const float* __restrict__ dinv,
                              const float* __restrict__ h,
                              float* __restrict__ out) {
    int warp = (blockIdx.x * blockDim.x + threadIdx.x) >> 5;
    int lane = threadIdx.x & 31;
    if (warp >= NE) return;
    int s = src[warp];
    int d = dst[warp];
    float nrm = dinv[s] * dinv[d];
    float4 v = reinterpret_cast<const float4*>(h + (size_t)s * HID)[lane];
    v.x *= nrm; v.y *= nrm; v.z *= nrm; v.w *= nrm;
    float* p = out + (size_t)d * HID + lane * 4;
    asm volatile("red.global.add.v4.f32 [%0], {%1, %2, %3, %4};"
                 :: "l"(p), "f"(v.x), "f"(v.y), "f"(v.z), "f"(v.w)
                 : "memory");
}

// ---------------- pipelined tf32 tensor-core GEMM ----------------------------
// C[M,N] = op(A)[M,K] @ B[K,N]. BM=128, BN=64, BK=32, 256 thr, 2-stage cp.async.
// Dynamic smem: As[2][128][36] then Bs[2][32][72] (uint32 words).

__device__ __forceinline__ void mma_tf32(float c[4], uint32_t a0, uint32_t a1,
                                         uint32_t a2, uint32_t a3,
                                         uint32_t b0, uint32_t b1) {
    asm volatile(
        "mma.sync.aligned.m16n8k8.row.col.f32.tf32.tf32.f32 "
        "{%0,%1,%2,%3}, {%4,%5,%6,%7}, {%8,%9}, {%0,%1,%2,%3};"
        : "+f"(c[0]), "+f"(c[1]), "+f"(c[2]), "+f"(c[3])
        : "r"(a0), "r"(a1), "r"(a2), "r"(a3), "r"(b0), "r"(b1));
}

__device__ __forceinline__ void cpasync16(uint32_t dst, const void* src, int sz) {
    asm volatile("cp.async.cg.shared.global [%0], [%1], 16, %2;"
                 :: "r"(dst), "l"(src), "r"(sz));
}
__device__ __forceinline__ void cp_commit() {
    asm volatile("cp.async.commit_group;");
}
__device__ __forceinline__ void cp_wait0() {
    asm volatile("cp.async.wait_group 0;");
}

#define APAD 36
#define BPAD 72
#define A_WORDS (2 * 128 * APAD)          // 9216 words
#define B_WORDS (2 * 32 * BPAD)           // 4608 words
#define GEMM_SMEM ((A_WORDS + B_WORDS) * 4)  // 55296 bytes

template<bool RELU_A, bool BIAS, bool SELF>
__global__ __launch_bounds__(256)
void tf32gemm(const float* __restrict__ A,
              const float* __restrict__ B,
              float* __restrict__ C,
              const float* __restrict__ bias,
              const float* __restrict__ dinv,
              float* __restrict__ O,
              int M, int N, int K, int ldb) {
    const int BM = 128, BK = 32;
    extern __shared__ __align__(16) uint32_t smem[];
    uint32_t (*As)[BM][APAD] = reinterpret_cast<uint32_t (*)[BM][APAD]>(smem);
    uint32_t (*Bs)[BK][BPAD] = reinterpret_cast<uint32_t (*)[BK][BPAD]>(smem + A_WORDS);

    int tid  = threadIdx.x;
    int lane = tid & 31;
    int wid  = tid >> 5;
    int gid  = lane >> 2;
    int tig  = lane & 3;
    int wm   = (wid & 3) * 32;
    int wn   = (wid >> 2) * 32;

    int row0 = blockIdx.y * BM;
    int col0 = blockIdx.x * 64;

    uint32_t sA = (uint32_t)__cvta_generic_to_shared(&As[0][0][0]);
    uint32_t sB = (uint32_t)__cvta_generic_to_shared(&Bs[0][0][0]);

    float acc[2][4][4];
    #pragma unroll
    for (int mt = 0; mt < 2; mt++)
        #pragma unroll
        for (int nt = 0; nt < 4; nt++)
            #pragma unroll
            for (int r = 0; r < 4; r++) acc[mt][nt][r] = 0.f;

    int aRow = tid >> 3;              // 0..31, +32 per chunk
    int aC4  = (tid & 7) * 4;
    int bRow = tid >> 4;              // 0..15, +16 for second
    int bC4  = (tid & 15) * 4;

    auto loadA = [&](int k0, int st) {
        #pragma unroll
        for (int i = 0; i < 4; i++) {
            int row = aRow + i * 32;
            int gr  = row0 + row;
            int grc = gr < M ? gr : M - 1;
            const float* src = A + (size_t)grc * K + k0 + aC4;
            uint32_t dst = sA + (((st * BM + row) * APAD) + aC4) * 4;
            cpasync16(dst, src, gr < M ? 16 : 0);
        }
    };
    auto loadB = [&](int k0, int st) {
        #pragma unroll
        for (int i = 0; i < 2; i++) {
            int row = bRow + i * 16;
            int gk  = k0 + row;
            int gc  = col0 + bC4;
            int rem = N - gc;
            int sz  = rem >= 4 ? 16 : (rem > 0 ? rem * 4 : 0);
            const float* src = B + (size_t)gk * ldb + (rem > 0 ? gc : 0);
            uint32_t dst = sB + (((st * BK + row) * BPAD) + bC4) * 4;
            cpasync16(dst, src, sz);
        }
    };

    int KT = K / BK;
    loadA(0, 0); loadB(0, 0);
    cp_commit();

    for (int kt = 0; kt < KT; kt++) {
        cp_wait0();
        __syncthreads();
        if (kt + 1 < KT) {
            loadA((kt + 1) * BK, (kt + 1) & 1);
            loadB((kt + 1) * BK, (kt + 1) & 1);
            cp_commit();
        }
        int st = kt & 1;
        #pragma unroll
        for (int kc = 0; kc < 4; kc++) {
            int ks = kc * 8;
            uint32_t a[2][4];
            #pragma unroll
            for (int mt = 0; mt < 2; mt++) {
                int r = wm + mt * 16 + gid;
                if (RELU_A) {
                    a[mt][0] = __float_as_uint(fmaxf(__uint_as_float(As[st][r    ][ks + tig    ]), 0.f));
                    a[mt][1] = __float_as_uint(fmaxf(__uint_as_float(As[st][r + 8][ks + tig    ]), 0.f));
                    a[mt][2] = __float_as_uint(fmaxf(__uint_as_float(As[st][r    ][ks + tig + 4]), 0.f));
                    a[mt][3] = __float_as_uint(fmaxf(__uint_as_float(As[st][r + 8][ks + tig + 4]), 0.f));
                } else {
                    a[mt][0] = As[st][r    ][ks + tig    ];
                    a[mt][1] = As[st][r + 8][ks + tig    ];
                    a[mt][2] = As[st][r    ][ks + tig + 4];
                    a[mt][3] = As[st][r + 8][ks + tig + 4];
                }
            }
            uint32_t b[4][2];
            #pragma unroll
            for (int nt = 0; nt < 4; nt++) {
                int c = wn + nt * 8 + gid;
                b[nt][0] = Bs[st][ks + tig    ][c];
                b[nt][1] = Bs[st][ks + tig + 4][c];
            }
            #pragma unroll
            for (int mt = 0; mt < 2; mt++)
                #pragma unroll
                for (int nt = 0; nt < 4; nt++)
                    mma_tf32(acc[mt][nt], a[mt][0], a[mt][1], a[mt][2], a[mt][3],
                             b[nt][0], b[nt][1]);
        }
        __syncthreads();
    }

    // epilogue
    #pragma unroll
    for (int mt = 0; mt < 2; mt++) {
        #pragma unroll
        for (int rr = 0; rr < 2; rr++) {
            int gr = row0 + wm + mt * 16 + gid + rr * 8;
            if (gr >= M) continue;
            float di2 = 0.f;
            if (SELF) { float di = dinv[gr]; di2 = di * di; }
            #pragma unroll
            for (int nt = 0; nt < 4; nt++) {
                int gc = col0 + wn + nt * 8 + tig * 2;
                float v0 = acc[mt][nt][rr * 2 + 0];
                float v1 = acc[mt][nt][rr * 2 + 1];
                if (gc + 1 < N) {
                    float* cp = C + (size_t)gr * N + gc;
                    if (BIAS) {
                        *reinterpret_cast<float2*>(cp) =
                            make_float2(v0 + bias[gc], v1 + bias[gc + 1]);
                    } else {
                        *reinterpret_cast<float2*>(cp) = make_float2(v0, v1);
                    }
                    if (SELF) {
                        float* op = O + (size_t)gr * N + gc;
                        *reinterpret_cast<float2*>(op) =
                            make_float2(bias[gc] + v0 * di2, bias[gc + 1] + v1 * di2);
                    }
                } else if (gc < N) {
                    C[(size_t)gr * N + gc] = BIAS ? v0 + bias[gc] : v0;
                    if (SELF) O[(size_t)gr * N + gc] = bias[gc] + v0 * di2;
                }
            }
        }
    }
}

// ---------------- launch ------------------------------------------------------
extern "C" void kernel_launch(void* const* d_in, const int* in_sizes, int n_in,
                              void* d_out, int out_size) {
    const float* x    = (const float*)d_in[0];
    const int*   ei   = (const int*)d_in[1];
    const float* text = (const float*)d_in[2];
    const float* W1   = (const float*)d_in[3];
    const float* b1   = (const float*)d_in[4];
    const float* W2   = (const float*)d_in[5];
    const float* b2   = (const float*)d_in[6];
    const float* Wc   = (const float*)d_in[7];
    const float* bc   = (const float*)d_in[8];
    float* out = (float*)d_out;

    float *deg, *h1, *o1, *h2, *o2, *tv;
    cudaGetSymbolAddress((void**)&deg, g_deg);
    cudaGetSymbolAddress((void**)&h1,  g_h1);
    cudaGetSymbolAddress((void**)&o1,  g_o1);
    cudaGetSymbolAddress((void**)&h2,  g_h2);
    cudaGetSymbolAddress((void**)&o2,  g_o2);
    cudaGetSymbolAddress((void**)&tv,  g_tvec);

    // raise dynamic smem cap (host-side attribute set; graph-capture safe)
    cudaFuncSetAttribute(tf32gemm<false, false, true>,
                         cudaFuncAttributeMaxDynamicSharedMemorySize, GEMM_SMEM);
    cudaFuncSetAttribute(tf32gemm<true, false, true>,
                         cudaFuncAttributeMaxDynamicSharedMemorySize, GEMM_SMEM);
    cudaFuncSetAttribute(tf32gemm<false, true, false>,
                         cudaFuncAttributeMaxDynamicSharedMemorySize, GEMM_SMEM);

    const int* srcp = ei;
    const int* dstp = ei + NE;

    deg_init <<<(NN + 255) / 256, 256>>>(deg);
    deg_count<<<(NE + 255) / 256, 256>>>(dstp, deg);
    deg_rsqrt<<<(NN + 255) / 256, 256>>>(deg);

    tvec_init<<<(OUTC + 127) / 128, 128>>>(bc, tv);
    dim3 gtp((OUTC + 127) / 128, TDIM / 128);
    text_proj_part<<<gtp, 128>>>(text, Wc, tv);

    dim3 gHid(2, (NN + 127) / 128);
    dim3 gOut(16, (NN + 127) / 128);

    // layer 1: h1 = x@W1 ; o1 = b1 + h1*dinv^2 (fused) ; scatter
    tf32gemm<false, false, true><<<gHid, 256, GEMM_SMEM>>>(x, W1, h1, b1, deg, o1,
                                                           NN, HID, INC, HID);
    scatter_edges<<<(NE * 32 + 255) / 256, 256>>>(srcp, dstp, deg, h1, o1);

    // layer 2: h2 = relu(o1)@W2 ; o2 = b2 + h2*dinv^2 (fused) ; scatter
    tf32gemm<true, false, true><<<gHid, 256, GEMM_SMEM>>>(o1, W2, h2, b2, deg, o2,
                                                          NN, HID, HID, HID);
    scatter_edges<<<(NE * 32 + 255) / 256, 256>>>(srcp, dstp, deg, h2, o2);

    // classifier: out = o2 @ Wc[:128] + tvec
    tf32gemm<false, true, false><<<gOut, 256, GEMM_SMEM>>>(o2, Wc, out, tv,
                                                           nullptr, nullptr,
                                                           NN, OUTC, HID, OUTC);
}

// round 6
// speedup vs baseline: 3.0541x; 1.1861x over previous
#include <cuda_runtime.h>
#include <cstdint>

#define NN 50000
#define NE 800000
#define INC 256
#define HID 128
#define OUTC 1000
#define TDIM 768

// ---------------- scratch ----------------------------------------------------
__device__ __align__(256) float g_deg[NN];
__device__ __align__(256) float g_h1[(size_t)NN * HID];
__device__ __align__(256) float g_o1[(size_t)NN * HID];
__device__ __align__(256) float g_h2[(size_t)NN * HID];
__device__ __align__(256) float g_o2[(size_t)NN * HID];
__device__ __align__(256) float g_tvec[1024];
__device__ __align__(256) int   g_ecnt[NN];
__device__ __align__(256) int   g_offs[NN + 1];
__device__ __align__(256) int   g_cursor[NN];
__device__ __align__(256) int   g_esrc[NE];
__device__ __align__(256) float g_ew[NE];

// ---------------- degree / norm ----------------------------------------------
__global__ void deg_init(float* deg) {
    int i = blockIdx.x * blockDim.x + threadIdx.x;
    if (i < NN) deg[i] = 1.0f;
}
__global__ void deg_count(const int* __restrict__ dst, float* deg) {
    int e = blockIdx.x * blockDim.x + threadIdx.x;
    if (e < NE) atomicAdd(&deg[dst[e]], 1.0f);
}
// deg -> deg^-1/2, and extract integer incoming-edge count (deg-1)
__global__ void deg_rsqrt_extract(float* deg, int* ecnt) {
    int i = blockIdx.x * blockDim.x + threadIdx.x;
    if (i >= NN) return;
    float d = deg[i];
    ecnt[i] = (int)d - 1;
    deg[i] = rsqrtf(d);
}

// single-block scan over ecnt -> offs (exclusive in offs[i], inclusive in offs[i+1])
// also writes cursor[i] = offs[i] for the fill pass.
__global__ void scan_offsets(const int* __restrict__ ecnt,
                             int* __restrict__ offs,
                             int* __restrict__ cursor) {
    __shared__ int warpsum[32];
    __shared__ int carry_s;
    int tid = threadIdx.x, lane = tid & 31, wid = tid >> 5;
    if (tid == 0) { carry_s = 0; offs[0] = 0; }
    __syncthreads();
    for (int chunk = 0; chunk < NN; chunk += 1024) {
        int i = chunk + tid;
        int v = (i < NN) ? ecnt[i] : 0;
        int x = v;
        #pragma unroll
        for (int d = 1; d < 32; d <<= 1) {
            int t = __shfl_up_sync(0xffffffffu, x, d);
            if (lane >= d) x += t;
        }
        if (lane == 31) warpsum[wid] = x;
        __syncthreads();
        if (wid == 0) {
            int y = warpsum[lane];
            #pragma unroll
            for (int d = 1; d < 32; d <<= 1) {
                int t = __shfl_up_sync(0xffffffffu, y, d);
                if (lane >= d) y += t;
            }
            warpsum[lane] = y;
        }
        __syncthreads();
        int incl = x + (wid > 0 ? warpsum[wid - 1] : 0) + carry_s;
        if (i < NN) { offs[i + 1] = incl; cursor[i] = incl - v; }
        __syncthreads();
        if (tid == 1023) carry_s = incl;
        __syncthreads();
    }
}

// bucket edges by destination: esrc[pos]=src, ew[pos]=dinv[src]*dinv[dst]
__global__ void fill_edges(const int* __restrict__ src,
                           const int* __restrict__ dst,
                           const float* __restrict__ dinv,
                           int* __restrict__ cursor,
                           int* __restrict__ esrc,
                           float* __restrict__ ew) {
    int e = blockIdx.x * blockDim.x + threadIdx.x;
    if (e >= NE) return;
    int s = src[e], d = dst[e];
    int pos = atomicAdd(&cursor[d], 1);
    esrc[pos] = s;
    ew[pos] = dinv[s] * dinv[d];
}

// ---------------- text branch ------------------------------------------------
__global__ void tvec_init(const float* __restrict__ bc, float* __restrict__ tvec) {
    int o = blockIdx.x * blockDim.x + threadIdx.x;
    if (o < OUTC) tvec[o] = bc[o];
}
__global__ void text_proj_part(const float* __restrict__ text,
                               const float* __restrict__ Wc,
                               float* __restrict__ tvec) {
    int o = blockIdx.x * 128 + threadIdx.x;
    int d0 = blockIdx.y * 128;
    if (o >= OUTC) return;
    float s = 0.f;
    #pragma unroll 8
    for (int d = d0; d < d0 + 128; d++)
        s += text[d] * Wc[(size_t)(HID + d) * OUTC + o];
    atomicAdd(&tvec[o], s);
}

// ---------------- CSR gather aggregation -------------------------------------
// one warp per destination node; o[d] already holds bias + self contribution;
// accumulate incoming messages in registers, write row once.
__global__ void gather_edges(const int* __restrict__ offs,
                             const int* __restrict__ esrc,
                             const float* __restrict__ ew,
                             const float* __restrict__ h,
                             float* __restrict__ o) {
    int warp = (blockIdx.x * blockDim.x + threadIdx.x) >> 5;
    int lane = threadIdx.x & 31;
    if (warp >= NN) return;
    int base = offs[warp], end = offs[warp + 1];
    float4 acc = reinterpret_cast<const float4*>(o + (size_t)warp * HID)[lane];
    for (int j0 = base; j0 < end; j0 += 32) {
        int e = j0 + lane;
        bool ok = e < end;
        int   s_l = ok ? esrc[e] : 0;
        float w_l = ok ? ew[e] : 0.f;
        int m = min(32, end - j0);
        for (int k = 0; k < m; k++) {
            int   ss = __shfl_sync(0xffffffffu, s_l, k);
            float ww = __shfl_sync(0xffffffffu, w_l, k);
            float4 v = reinterpret_cast<const float4*>(h + (size_t)ss * HID)[lane];
            acc.x += v.x * ww; acc.y += v.y * ww;
            acc.z += v.z * ww; acc.w += v.w * ww;
        }
    }
    reinterpret_cast<float4*>(o + (size_t)warp * HID)[lane] = acc;
}

// ---------------- pipelined tf32 tensor-core GEMM ----------------------------
__device__ __forceinline__ void mma_tf32(float c[4], uint32_t a0, uint32_t a1,
                                         uint32_t a2, uint32_t a3,
                                         uint32_t b0, uint32_t b1) {
    asm volatile(
        "mma.sync.aligned.m16n8k8.row.col.f32.tf32.tf32.f32 "
        "{%0,%1,%2,%3}, {%4,%5,%6,%7}, {%8,%9}, {%0,%1,%2,%3};"
        : "+f"(c[0]), "+f"(c[1]), "+f"(c[2]), "+f"(c[3])
        : "r"(a0), "r"(a1), "r"(a2), "r"(a3), "r"(b0), "r"(b1));
}
__device__ __forceinline__ void cpasync16(uint32_t dst, const void* src, int sz) {
    asm volatile("cp.async.cg.shared.global [%0], [%1], 16, %2;"
                 :: "r"(dst), "l"(src), "r"(sz));
}
__device__ __forceinline__ void cp_commit() { asm volatile("cp.async.commit_group;"); }
__device__ __forceinline__ void cp_wait0()  { asm volatile("cp.async.wait_group 0;"); }

#define APAD 36
#define A_WORDS (2 * 128 * APAD)
#define BPAD(BN) ((BN) + 8)
#define B_WORDS(BN) (2 * 32 * BPAD(BN))
#define GEMM_SMEM(BN) ((A_WORDS + B_WORDS(BN)) * 4)

template<bool RELU_A, bool BIAS, bool SELF, int BN>
__global__ __launch_bounds__(256)
void tf32gemm(const float* __restrict__ A,
              const float* __restrict__ B,
              float* __restrict__ C,
              const float* __restrict__ bias,
              const float* __restrict__ dinv,
              float* __restrict__ O,
              int M, int N, int K, int ldb) {
    const int BM = 128, BK = 32;
    const int NT = BN / 16;                 // n-tiles of 8 per warp (2 warps in n)
    extern __shared__ __align__(16) uint32_t smem[];
    uint32_t (*As)[BM][APAD] = reinterpret_cast<uint32_t (*)[BM][APAD]>(smem);
    uint32_t (*Bs)[BK][BPAD(BN)] =
        reinterpret_cast<uint32_t (*)[BK][BPAD(BN)]>(smem + A_WORDS);

    int tid  = threadIdx.x;
    int lane = tid & 31;
    int wid  = tid >> 5;
    int gid  = lane >> 2;
    int tig  = lane & 3;
    int wm   = (wid & 3) * 32;
    int wn   = (wid >> 2) * (BN / 2);

    int row0 = blockIdx.y * BM;
    int col0 = blockIdx.x * BN;

    uint32_t sA = (uint32_t)__cvta_generic_to_shared(&As[0][0][0]);
    uint32_t sB = (uint32_t)__cvta_generic_to_shared(&Bs[0][0][0]);

    float acc[2][NT][4];
    #pragma unroll
    for (int mt = 0; mt < 2; mt++)
        #pragma unroll
        for (int nt = 0; nt < NT; nt++)
            #pragma unroll
            for (int r = 0; r < 4; r++) acc[mt][nt][r] = 0.f;

    int aRow = tid >> 3;
    int aC4  = (tid & 7) * 4;
    const int BV = BN / 8;                 // float4 per B row / 4... loads per thread
    int bRow = tid / (BN / 4);
    int bC4  = (tid % (BN / 4)) * 4;
    const int BROWSTEP = 256 / (BN / 4);   // rows covered per pass

    auto loadA = [&](int k0, int st) {
        #pragma unroll
        for (int i = 0; i < 4; i++) {
            int row = aRow + i * 32;
            int gr  = row0 + row;
            int grc = gr < M ? gr : M - 1;
            const float* src = A + (size_t)grc * K + k0 + aC4;
            uint32_t dst = sA + (((st * BM + row) * APAD) + aC4) * 4;
            cpasync16(dst, src, gr < M ? 16 : 0);
        }
    };
    auto loadB = [&](int k0, int st) {
        #pragma unroll
        for (int i = 0; i < 32 / BROWSTEP; i++) {
            int row = bRow + i * BROWSTEP;
            int gk  = k0 + row;
            int gc  = col0 + bC4;
            int rem = N - gc;
            int sz  = rem >= 4 ? 16 : (rem > 0 ? rem * 4 : 0);
            const float* src = B + (size_t)gk * ldb + (rem > 0 ? gc : 0);
            uint32_t dst = sB + (((st * BK + row) * BPAD(BN)) + bC4) * 4;
            cpasync16(dst, src, sz);
        }
    };

    int KT = K / BK;
    loadA(0, 0); loadB(0, 0);
    cp_commit();

    for (int kt = 0; kt < KT; kt++) {
        cp_wait0();
        __syncthreads();
        if (kt + 1 < KT) {
            loadA((kt + 1) * BK, (kt + 1) & 1);
            loadB((kt + 1) * BK, (kt + 1) & 1);
            cp_commit();
        }
        int st = kt & 1;
        #pragma unroll
        for (int kc = 0; kc < 4; kc++) {
            int ks = kc * 8;
            uint32_t a[2][4];
            #pragma unroll
            for (int mt = 0; mt < 2; mt++) {
                int r = wm + mt * 16 + gid;
                if (RELU_A) {
                    a[mt][0] = __float_as_uint(fmaxf(__uint_as_float(As[st][r    ][ks + tig    ]), 0.f));
                    a[mt][1] = __float_as_uint(fmaxf(__uint_as_float(As[st][r + 8][ks + tig    ]), 0.f));
                    a[mt][2] = __float_as_uint(fmaxf(__uint_as_float(As[st][r    ][ks + tig + 4]), 0.f));
                    a[mt][3] = __float_as_uint(fmaxf(__uint_as_float(As[st][r + 8][ks + tig + 4]), 0.f));
                } else {
                    a[mt][0] = As[st][r    ][ks + tig    ];
                    a[mt][1] = As[st][r + 8][ks + tig    ];
                    a[mt][2] = As[st][r    ][ks + tig + 4];
                    a[mt][3] = As[st][r + 8][ks + tig + 4];
                }
            }
            uint32_t b[NT][2];
            #pragma unroll
            for (int nt = 0; nt < NT; nt++) {
                int c = wn + nt * 8 + gid;
                b[nt][0] = Bs[st][ks + tig    ][c];
                b[nt][1] = Bs[st][ks + tig + 4][c];
            }
            #pragma unroll
            for (int mt = 0; mt < 2; mt++)
                #pragma unroll
                for (int nt = 0; nt < NT; nt++)
                    mma_tf32(acc[mt][nt], a[mt][0], a[mt][1], a[mt][2], a[mt][3],
                             b[nt][0], b[nt][1]);
        }
        __syncthreads();
    }

    #pragma unroll
    for (int mt = 0; mt < 2; mt++) {
        #pragma unroll
        for (int rr = 0; rr < 2; rr++) {
            int gr = row0 + wm + mt * 16 + gid + rr * 8;
            if (gr >= M) continue;
            float di2 = 0.f;
            if (SELF) { float di = dinv[gr]; di2 = di * di; }
            #pragma unroll
            for (int nt = 0; nt < NT; nt++) {
                int gc = col0 + wn + nt * 8 + tig * 2;
                float v0 = acc[mt][nt][rr * 2 + 0];
                float v1 = acc[mt][nt][rr * 2 + 1];
                if (gc + 1 < N) {
                    float* cp = C + (size_t)gr * N + gc;
                    if (BIAS) {
                        *reinterpret_cast<float2*>(cp) =
                            make_float2(v0 + bias[gc], v1 + bias[gc + 1]);
                    } else {
                        *reinterpret_cast<float2*>(cp) = make_float2(v0, v1);
                    }
                    if (SELF) {
                        float* op = O + (size_t)gr * N + gc;
                        *reinterpret_cast<float2*>(op) =
                            make_float2(bias[gc] + v0 * di2, bias[gc + 1] + v1 * di2);
                    }
                } else if (gc < N) {
                    C[(size_t)gr * N + gc] = BIAS ? v0 + bias[gc] : v0;
                    if (SELF) O[(size_t)gr * N + gc] = bias[gc] + v0 * di2;
                }
            }
        }
    }
}

// ---------------- launch ------------------------------------------------------
extern "C" void kernel_launch(void* const* d_in, const int* in_sizes, int n_in,
                              void* d_out, int out_size) {
    const float* x    = (const float*)d_in[0];
    const int*   ei   = (const int*)d_in[1];
    const float* text = (const float*)d_in[2];
    const float* W1   = (const float*)d_in[3];
    const float* b1   = (const float*)d_in[4];
    const float* W2   = (const float*)d_in[5];
    const float* b2   = (const float*)d_in[6];
    const float* Wc   = (const float*)d_in[7];
    const float* bc   = (const float*)d_in[8];
    float* out = (float*)d_out;

    float *deg, *h1, *o1, *h2, *o2, *tv, *ew;
    int *ecnt, *offs, *cursor, *esrc;
    cudaGetSymbolAddress((void**)&deg,   g_deg);
    cudaGetSymbolAddress((void**)&h1,    g_h1);
    cudaGetSymbolAddress((void**)&o1,    g_o1);
    cudaGetSymbolAddress((void**)&h2,    g_h2);
    cudaGetSymbolAddress((void**)&o2,    g_o2);
    cudaGetSymbolAddress((void**)&tv,    g_tvec);
    cudaGetSymbolAddress((void**)&ecnt,  g_ecnt);
    cudaGetSymbolAddress((void**)&offs,  g_offs);
    cudaGetSymbolAddress((void**)&cursor,g_cursor);
    cudaGetSymbolAddress((void**)&esrc,  g_esrc);
    cudaGetSymbolAddress((void**)&ew,    g_ew);

    cudaFuncSetAttribute(tf32gemm<false, false, true, 64>,
                         cudaFuncAttributeMaxDynamicSharedMemorySize, GEMM_SMEM(64));
    cudaFuncSetAttribute(tf32gemm<true, false, true, 64>,
                         cudaFuncAttributeMaxDynamicSharedMemorySize, GEMM_SMEM(64));
    cudaFuncSetAttribute(tf32gemm<false, true, false, 128>,
                         cudaFuncAttributeMaxDynamicSharedMemorySize, GEMM_SMEM(128));

    const int* srcp = ei;
    const int* dstp = ei + NE;

    // degree + normalization + CSR build
    deg_init <<<(NN + 255) / 256, 256>>>(deg);
    deg_count<<<(NE + 255) / 256, 256>>>(dstp, deg);
    deg_rsqrt_extract<<<(NN + 255) / 256, 256>>>(deg, ecnt);
    scan_offsets<<<1, 1024>>>(ecnt, offs, cursor);
    fill_edges<<<(NE + 255) / 256, 256>>>(srcp, dstp, deg, cursor, esrc, ew);

    // text branch
    tvec_init<<<(OUTC + 127) / 128, 128>>>(bc, tv);
    dim3 gtp((OUTC + 127) / 128, TDIM / 128);
    text_proj_part<<<gtp, 128>>>(text, Wc, tv);

    dim3 gHid(2, (NN + 127) / 128);
    dim3 gOut((OUTC + 127) / 128, (NN + 127) / 128);   // (8, 391)
    int gatherBlocks = (NN * 32 + 255) / 256;

    // layer 1
    tf32gemm<false, false, true, 64><<<gHid, 256, GEMM_SMEM(64)>>>(
        x, W1, h1, b1, deg, o1, NN, HID, INC, HID);
    gather_edges<<<gatherBlocks, 256>>>(offs, esrc, ew, h1, o1);

    // layer 2
    tf32gemm<true, false, true, 64><<<gHid, 256, GEMM_SMEM(64)>>>(
        o1, W2, h2, b2, deg, o2, NN, HID, HID, HID);
    gather_edges<<<gatherBlocks, 256>>>(offs, esrc, ew, h2, o2);

    // classifier
    tf32gemm<false, true, false, 128><<<gOut, 256, GEMM_SMEM(128)>>>(
        o2, Wc, out, tv, nullptr, nullptr, NN, OUTC, HID, OUTC);
}

// round 7
// speedup vs baseline: 3.6221x; 1.1860x over previous
#include <cuda_runtime.h>
#include <cuda_fp16.h>
#include <cstdint>

#define NN 50000
#define NE 800000
#define INC 256
#define HID 128
#define OUTC 1000
#define TDIM 768

// ---------------- scratch ----------------------------------------------------
__device__ __align__(256) float  g_deg[NN];
__device__ __align__(256) __half g_h1[(size_t)NN * HID];
__device__ __align__(256) float  g_o1[(size_t)NN * HID];
__device__ __align__(256) __half g_h2[(size_t)NN * HID];
__device__ __align__(256) float  g_o2[(size_t)NN * HID];
__device__ __align__(256) float  g_tvec[1024];
__device__ __align__(256) int    g_ecnt[NN];
__device__ __align__(256) int    g_offs[NN];
__device__ __align__(256) int    g_cursor[NN];
__device__ __align__(256) int    g_esrc[NE];
__device__ __align__(256) float  g_ew[NE];
__device__ int g_counter;

// ---------------- degree / norm / CSR ----------------------------------------
__global__ void deg_init(float* deg, int* counter) {
    int i = blockIdx.x * blockDim.x + threadIdx.x;
    if (i == 0) *counter = 0;
    if (i < NN) deg[i] = 1.0f;
}
__global__ void deg_count(const int* __restrict__ dst, float* deg) {
    int e = blockIdx.x * blockDim.x + threadIdx.x;
    if (e < NE) atomicAdd(&deg[dst[e]], 1.0f);
}
// deg -> deg^-1/2, extract integer incoming count (deg-1)
__global__ void deg_rsqrt_extract(float* deg, int* ecnt) {
    int i = blockIdx.x * blockDim.x + threadIdx.x;
    if (i >= NN) return;
    float d = deg[i];
    ecnt[i] = (int)d - 1;
    deg[i] = rsqrtf(d);
}
// segment allocation via atomic counter (ordering irrelevant for gather)
__global__ void alloc_offsets(const int* __restrict__ ecnt,
                              int* __restrict__ offs,
                              int* __restrict__ cursor,
                              int* counter) {
    int i = blockIdx.x * blockDim.x + threadIdx.x;
    if (i >= NN) return;
    int base = atomicAdd(counter, ecnt[i]);
    offs[i] = base;
    cursor[i] = base;
}
// bucket edges by destination
__global__ void fill_edges(const int* __restrict__ src,
                           const int* __restrict__ dst,
                           const float* __restrict__ dinv,
                           int* __restrict__ cursor,
                           int* __restrict__ esrc,
                           float* __restrict__ ew) {
    int e = blockIdx.x * blockDim.x + threadIdx.x;
    if (e >= NE) return;
    int s = src[e], d = dst[e];
    int pos = atomicAdd(&cursor[d], 1);
    esrc[pos] = s;
    ew[pos] = dinv[s] * dinv[d];
}

// ---------------- text branch ------------------------------------------------
__global__ void tvec_init(const float* __restrict__ bc, float* __restrict__ tvec) {
    int o = blockIdx.x * blockDim.x + threadIdx.x;
    if (o < OUTC) tvec[o] = bc[o];
}
__global__ void text_proj_part(const float* __restrict__ text,
                               const float* __restrict__ Wc,
                               float* __restrict__ tvec) {
    int o = blockIdx.x * 128 + threadIdx.x;
    int d0 = blockIdx.y * 128;
    if (o >= OUTC) return;
    float s = 0.f;
    #pragma unroll 8
    for (int d = d0; d < d0 + 128; d++)
        s += text[d] * Wc[(size_t)(HID + d) * OUTC + o];
    atomicAdd(&tvec[o], s);
}

// ---------------- CSR gather (h in fp16) -------------------------------------
// one warp per destination; o already holds bias + self; accumulate in fp32.
__global__ void gather_edges(const int* __restrict__ offs,
                             const int* __restrict__ ecnt,
                             const int* __restrict__ esrc,
                             const float* __restrict__ ew,
                             const __half* __restrict__ h,
                             float* __restrict__ o) {
    int warp = (blockIdx.x * blockDim.x + threadIdx.x) >> 5;
    int lane = threadIdx.x & 31;
    if (warp >= NN) return;
    int base = offs[warp];
    int end  = base + ecnt[warp];
    float4 acc = reinterpret_cast<const float4*>(o + (size_t)warp * HID)[lane];
    for (int j0 = base; j0 < end; j0 += 32) {
        int e = j0 + lane;
        bool ok = e < end;
        int   s_l = ok ? esrc[e] : 0;
        float w_l = ok ? ew[e] : 0.f;
        int m = min(32, end - j0);
        for (int k = 0; k < m; k++) {
            int   ss = __shfl_sync(0xffffffffu, s_l, k);
            float ww = __shfl_sync(0xffffffffu, w_l, k);
            uint2 raw = reinterpret_cast<const uint2*>(h + (size_t)ss * HID)[lane];
            float2 f0 = __half22float2(*reinterpret_cast<__half2*>(&raw.x));
            float2 f1 = __half22float2(*reinterpret_cast<__half2*>(&raw.y));
            acc.x += f0.x * ww; acc.y += f0.y * ww;
            acc.z += f1.x * ww; acc.w += f1.y * ww;
        }
    }
    reinterpret_cast<float4*>(o + (size_t)warp * HID)[lane] = acc;
}

// ---------------- pipelined tf32 tensor-core GEMM ----------------------------
__device__ __forceinline__ void mma_tf32(float c[4], uint32_t a0, uint32_t a1,
                                         uint32_t a2, uint32_t a3,
                                         uint32_t b0, uint32_t b1) {
    asm volatile(
        "mma.sync.aligned.m16n8k8.row.col.f32.tf32.tf32.f32 "
        "{%0,%1,%2,%3}, {%4,%5,%6,%7}, {%8,%9}, {%0,%1,%2,%3};"
        : "+f"(c[0]), "+f"(c[1]), "+f"(c[2]), "+f"(c[3])
        : "r"(a0), "r"(a1), "r"(a2), "r"(a3), "r"(b0), "r"(b1));
}
__device__ __forceinline__ void cpasync16(uint32_t dst, const void* src, int sz) {
    asm volatile("cp.async.cg.shared.global [%0], [%1], 16, %2;"
                 :: "r"(dst), "l"(src), "r"(sz));
}
__device__ __forceinline__ void cp_commit() { asm volatile("cp.async.commit_group;"); }
__device__ __forceinline__ void cp_wait0()  { asm volatile("cp.async.wait_group 0;"); }

#define APAD 36
#define A_WORDS (2 * 128 * APAD)
#define BPAD(BN) ((BN) + 8)
#define B_WORDS(BN) (2 * 32 * BPAD(BN))
#define GEMM_SMEM(BN) ((A_WORDS + B_WORDS(BN)) * 4)

// SELF: C is __half* (h output, half2 stores) and O fp32 = bias + v*dinv^2.
// !SELF: C is float*; BIAS adds bias to C.
template<bool RELU_A, bool BIAS, bool SELF, int BN>
__global__ __launch_bounds__(256)
void tf32gemm(const float* __restrict__ A,
              const float* __restrict__ B,
              void* __restrict__ Cv,
              const float* __restrict__ bias,
              const float* __restrict__ dinv,
              float* __restrict__ O,
              int M, int N, int K, int ldb) {
    const int BM = 128, BK = 32;
    const int NT = BN / 16;
    extern __shared__ __align__(16) uint32_t smem[];
    uint32_t (*As)[BM][APAD] = reinterpret_cast<uint32_t (*)[BM][APAD]>(smem);
    uint32_t (*Bs)[BK][BPAD(BN)] =
        reinterpret_cast<uint32_t (*)[BK][BPAD(BN)]>(smem + A_WORDS);

    int tid  = threadIdx.x;
    int lane = tid & 31;
    int wid  = tid >> 5;
    int gid  = lane >> 2;
    int tig  = lane & 3;
    int wm   = (wid & 3) * 32;
    int wn   = (wid >> 2) * (BN / 2);

    int row0 = blockIdx.y * BM;
    int col0 = blockIdx.x * BN;

    uint32_t sA = (uint32_t)__cvta_generic_to_shared(&As[0][0][0]);
    uint32_t sB = (uint32_t)__cvta_generic_to_shared(&Bs[0][0][0]);

    float acc[2][NT][4];
    #pragma unroll
    for (int mt = 0; mt < 2; mt++)
        #pragma unroll
        for (int nt = 0; nt < NT; nt++)
            #pragma unroll
            for (int r = 0; r < 4; r++) acc[mt][nt][r] = 0.f;

    int aRow = tid >> 3;
    int aC4  = (tid & 7) * 4;
    int bRow = tid / (BN / 4);
    int bC4  = (tid % (BN / 4)) * 4;
    const int BROWSTEP = 256 / (BN / 4);

    auto loadA = [&](int k0, int st) {
        #pragma unroll
        for (int i = 0; i < 4; i++) {
            int row = aRow + i * 32;
            int gr  = row0 + row;
            int grc = gr < M ? gr : M - 1;
            const float* src = A + (size_t)grc * K + k0 + aC4;
            uint32_t dst = sA + (((st * BM + row) * APAD) + aC4) * 4;
            cpasync16(dst, src, gr < M ? 16 : 0);
        }
    };
    auto loadB = [&](int k0, int st) {
        #pragma unroll
        for (int i = 0; i < 32 / BROWSTEP; i++) {
            int row = bRow + i * BROWSTEP;
            int gk  = k0 + row;
            int gc  = col0 + bC4;
            int rem = N - gc;
            int sz  = rem >= 4 ? 16 : (rem > 0 ? rem * 4 : 0);
            const float* src = B + (size_t)gk * ldb + (rem > 0 ? gc : 0);
            uint32_t dst = sB + (((st * BK + row) * BPAD(BN)) + bC4) * 4;
            cpasync16(dst, src, sz);
        }
    };

    int KT = K / BK;
    loadA(0, 0); loadB(0, 0);
    cp_commit();

    for (int kt = 0; kt < KT; kt++) {
        cp_wait0();
        __syncthreads();
        if (kt + 1 < KT) {
            loadA((kt + 1) * BK, (kt + 1) & 1);
            loadB((kt + 1) * BK, (kt + 1) & 1);
            cp_commit();
        }
        int st = kt & 1;
        #pragma unroll
        for (int kc = 0; kc < 4; kc++) {
            int ks = kc * 8;
            uint32_t a[2][4];
            #pragma unroll
            for (int mt = 0; mt < 2; mt++) {
                int r = wm + mt * 16 + gid;
                if (RELU_A) {
                    a[mt][0] = __float_as_uint(fmaxf(__uint_as_float(As[st][r    ][ks + tig    ]), 0.f));
                    a[mt][1] = __float_as_uint(fmaxf(__uint_as_float(As[st][r + 8][ks + tig    ]), 0.f));
                    a[mt][2] = __float_as_uint(fmaxf(__uint_as_float(As[st][r    ][ks + tig + 4]), 0.f));
                    a[mt][3] = __float_as_uint(fmaxf(__uint_as_float(As[st][r + 8][ks + tig + 4]), 0.f));
                } else {
                    a[mt][0] = As[st][r    ][ks + tig    ];
                    a[mt][1] = As[st][r + 8][ks + tig    ];
                    a[mt][2] = As[st][r    ][ks + tig + 4];
                    a[mt][3] = As[st][r + 8][ks + tig + 4];
                }
            }
            uint32_t b[NT][2];
            #pragma unroll
            for (int nt = 0; nt < NT; nt++) {
                int c = wn + nt * 8 + gid;
                b[nt][0] = Bs[st][ks + tig    ][c];
                b[nt][1] = Bs[st][ks + tig + 4][c];
            }
            #pragma unroll
            for (int mt = 0; mt < 2; mt++)
                #pragma unroll
                for (int nt = 0; nt < NT; nt++)
                    mma_tf32(acc[mt][nt], a[mt][0], a[mt][1], a[mt][2], a[mt][3],
                             b[nt][0], b[nt][1]);
        }
        __syncthreads();
    }

    #pragma unroll
    for (int mt = 0; mt < 2; mt++) {
        #pragma unroll
        for (int rr = 0; rr < 2; rr++) {
            int gr = row0 + wm + mt * 16 + gid + rr * 8;
            if (gr >= M) continue;
            float di2 = 0.f;
            if (SELF) { float di = dinv[gr]; di2 = di * di; }
            #pragma unroll
            for (int nt = 0; nt < NT; nt++) {
                int gc = col0 + wn + nt * 8 + tig * 2;
                float v0 = acc[mt][nt][rr * 2 + 0];
                float v1 = acc[mt][nt][rr * 2 + 1];
                if (SELF) {
                    // h output (half2) + o output (fp32); N=128 -> always in-bounds pair
                    __half* Ch = (__half*)Cv;
                    *reinterpret_cast<__half2*>(Ch + (size_t)gr * N + gc) =
                        __floats2half2_rn(v0, v1);
                    float* op = O + (size_t)gr * N + gc;
                    *reinterpret_cast<float2*>(op) =
                        make_float2(bias[gc] + v0 * di2, bias[gc + 1] + v1 * di2);
                } else {
                    float* Cf = (float*)Cv;
                    if (gc + 1 < N) {
                        float* cp = Cf + (size_t)gr * N + gc;
                        if (BIAS) {
                            *reinterpret_cast<float2*>(cp) =
                                make_float2(v0 + bias[gc], v1 + bias[gc + 1]);
                        } else {
                            *reinterpret_cast<float2*>(cp) = make_float2(v0, v1);
                        }
                    } else if (gc < N) {
                        Cf[(size_t)gr * N + gc] = BIAS ? v0 + bias[gc] : v0;
                    }
                }
            }
        }
    }
}

// ---------------- launch ------------------------------------------------------
extern "C" void kernel_launch(void* const* d_in, const int* in_sizes, int n_in,
                              void* d_out, int out_size) {
    const float* x    = (const float*)d_in[0];
    const int*   ei   = (const int*)d_in[1];
    const float* text = (const float*)d_in[2];
    const float* W1   = (const float*)d_in[3];
    const float* b1   = (const float*)d_in[4];
    const float* W2   = (const float*)d_in[5];
    const float* b2   = (const float*)d_in[6];
    const float* Wc   = (const float*)d_in[7];
    const float* bc   = (const float*)d_in[8];
    float* out = (float*)d_out;

    float *deg, *o1, *o2, *tv, *ew;
    __half *h1, *h2;
    int *ecnt, *offs, *cursor, *esrc, *counter;
    cudaGetSymbolAddress((void**)&deg,    g_deg);
    cudaGetSymbolAddress((void**)&h1,     g_h1);
    cudaGetSymbolAddress((void**)&o1,     g_o1);
    cudaGetSymbolAddress((void**)&h2,     g_h2);
    cudaGetSymbolAddress((void**)&o2,     g_o2);
    cudaGetSymbolAddress((void**)&tv,     g_tvec);
    cudaGetSymbolAddress((void**)&ecnt,   g_ecnt);
    cudaGetSymbolAddress((void**)&offs,   g_offs);
    cudaGetSymbolAddress((void**)&cursor, g_cursor);
    cudaGetSymbolAddress((void**)&esrc,   g_esrc);
    cudaGetSymbolAddress((void**)&ew,     g_ew);
    cudaGetSymbolAddress((void**)&counter,g_counter);

    cudaFuncSetAttribute(tf32gemm<false, false, true, 64>,
                         cudaFuncAttributeMaxDynamicSharedMemorySize, GEMM_SMEM(64));
    cudaFuncSetAttribute(tf32gemm<true, false, true, 64>,
                         cudaFuncAttributeMaxDynamicSharedMemorySize, GEMM_SMEM(64));
    cudaFuncSetAttribute(tf32gemm<false, true, false, 128>,
                         cudaFuncAttributeMaxDynamicSharedMemorySize, GEMM_SMEM(128));

    const int* srcp = ei;
    const int* dstp = ei + NE;

    // degree + normalization + CSR build (atomic segment allocation, no scan)
    deg_init <<<(NN + 255) / 256, 256>>>(deg, counter);
    deg_count<<<(NE + 255) / 256, 256>>>(dstp, deg);
    deg_rsqrt_extract<<<(NN + 255) / 256, 256>>>(deg, ecnt);
    alloc_offsets<<<(NN + 255) / 256, 256>>>(ecnt, offs, cursor, counter);
    fill_edges<<<(NE + 255) / 256, 256>>>(srcp, dstp, deg, cursor, esrc, ew);

    // text branch
    tvec_init<<<(OUTC + 127) / 128, 128>>>(bc, tv);
    dim3 gtp((OUTC + 127) / 128, TDIM / 128);
    text_proj_part<<<gtp, 128>>>(text, Wc, tv);

    dim3 gHid(2, (NN + 127) / 128);
    dim3 gOut((OUTC + 127) / 128, (NN + 127) / 128);
    int gatherBlocks = (NN * 32 + 255) / 256;

    // layer 1: h1(half) = x@W1 ; o1 = b1 + h1*dinv^2 ; gather
    tf32gemm<false, false, true, 64><<<gHid, 256, GEMM_SMEM(64)>>>(
        x, W1, h1, b1, deg, o1, NN, HID, INC, HID);
    gather_edges<<<gatherBlocks, 256>>>(offs, ecnt, esrc, ew, h1, o1);

    // layer 2: h2(half) = relu(o1)@W2 ; o2 = b2 + h2*dinv^2 ; gather
    tf32gemm<true, false, true, 64><<<gHid, 256, GEMM_SMEM(64)>>>(
        o1, W2, h2, b2, deg, o2, NN, HID, HID, HID);
    gather_edges<<<gatherBlocks, 256>>>(offs, ecnt, esrc, ew, h2, o2);

    // classifier: out = o2 @ Wc[:128] + tvec
    tf32gemm<false, true, false, 128><<<gOut, 256, GEMM_SMEM(128)>>>(
        o2, Wc, out, tv, nullptr, nullptr, NN, OUTC, HID, OUTC);
}

// round 9
// speedup vs baseline: 3.8828x; 1.0720x over previous
#include <cuda_runtime.h>
#include <cuda_fp16.h>
#include <cstdint>

#define NN 50000
#define NE 800000
#define INC 256
#define HID 128
#define OUTC 1000
#define TDIM 768

// ---------------- scratch ----------------------------------------------------
__device__ __align__(256) float  g_deg[NN];
__device__ __align__(256) __half g_h1[(size_t)NN * HID];
__device__ __align__(256) float  g_o1[(size_t)NN * HID];
__device__ __align__(256) __half g_h2[(size_t)NN * HID];
__device__ __align__(256) float  g_o2[(size_t)NN * HID];
__device__ __align__(256) float  g_tvec[1024];
__device__ __align__(256) int    g_ecnt[NN];
__device__ __align__(256) int    g_offs[NN];
__device__ __align__(256) int    g_cursor[NN];
__device__ __align__(256) int    g_esrc[NE];
__device__ __align__(256) float  g_ew[NE];
__device__ int g_counter;

// ---------------- prep kernels ------------------------------------------------
// init: deg=1 (self-loop), tvec=bc, counter=0
__global__ void init_all(float* deg, float* tvec, const float* __restrict__ bc,
                         int* counter) {
    int i = blockIdx.x * blockDim.x + threadIdx.x;
    if (i == 0) *counter = 0;
    if (i < NN) deg[i] = 1.0f;
    if (i < OUTC) tvec[i] = bc[i];
}
__global__ void deg_count(const int* __restrict__ dst, float* deg) {
    int e = blockIdx.x * blockDim.x + threadIdx.x;
    if (e < NE) atomicAdd(&deg[dst[e]], 1.0f);
}
// deg -> deg^-1/2, ecnt, and CSR segment allocation (atomic; order irrelevant)
__global__ void rsqrt_alloc(float* deg, int* ecnt, int* offs, int* cursor,
                            int* counter) {
    int i = blockIdx.x * blockDim.x + threadIdx.x;
    if (i >= NN) return;
    float d = deg[i];
    int c = (int)d - 1;
    ecnt[i] = c;
    deg[i] = rsqrtf(d);
    int base = atomicAdd(counter, c);
    offs[i] = base;
    cursor[i] = base;
}
__global__ void fill_edges(const int* __restrict__ src,
                           const int* __restrict__ dst,
                           const float* __restrict__ dinv,
                           int* __restrict__ cursor,
                           int* __restrict__ esrc,
                           float* __restrict__ ew) {
    int e = blockIdx.x * blockDim.x + threadIdx.x;
    if (e >= NE) return;
    int s = src[e], d = dst[e];
    int pos = atomicAdd(&cursor[d], 1);
    esrc[pos] = s;
    ew[pos] = dinv[s] * dinv[d];
}
__global__ void text_proj_part(const float* __restrict__ text,
                               const float* __restrict__ Wc,
                               float* __restrict__ tvec) {
    int o = blockIdx.x * 128 + threadIdx.x;
    int d0 = blockIdx.y * 128;
    if (o >= OUTC) return;
    float s = 0.f;
    #pragma unroll 8
    for (int d = d0; d < d0 + 128; d++)
        s += text[d] * Wc[(size_t)(HID + d) * OUTC + o];
    atomicAdd(&tvec[o], s);
}

// ---------------- CSR gather (h fp16, self+bias fused) -----------------------
// one warp per destination node: o[d] = bias + h[d]*dinv[d]^2 + sum_in h[s]*w
__global__ void gather_edges(const int* __restrict__ offs,
                             const int* __restrict__ ecnt,
                             const int* __restrict__ esrc,
                             const float* __restrict__ ew,
                             const __half* __restrict__ h,
                             const float* __restrict__ dinv,
                             const float* __restrict__ bias,
                             float* __restrict__ o) {
    int warp = (blockIdx.x * blockDim.x + threadIdx.x) >> 5;
    int lane = threadIdx.x & 31;
    if (warp >= NN) return;
    int base = offs[warp];
    int end  = base + ecnt[warp];
    float di = dinv[warp];
    float di2 = di * di;
    float4 acc = reinterpret_cast<const float4*>(bias)[lane];
    {   // self contribution
        uint2 raw = reinterpret_cast<const uint2*>(h + (size_t)warp * HID)[lane];
        float2 f0 = __half22float2(*reinterpret_cast<__half2*>(&raw.x));
        float2 f1 = __half22float2(*reinterpret_cast<__half2*>(&raw.y));
        acc.x += f0.x * di2; acc.y += f0.y * di2;
        acc.z += f1.x * di2; acc.w += f1.y * di2;
    }
    for (int j0 = base; j0 < end; j0 += 32) {
        int e = j0 + lane;
        bool ok = e < end;
        int   s_l = ok ? esrc[e] : 0;
        float w_l = ok ? ew[e] : 0.f;
        int m = min(32, end - j0);
        #pragma unroll 4
        for (int k = 0; k < m; k++) {
            int   ss = __shfl_sync(0xffffffffu, s_l, k);
            float ww = __shfl_sync(0xffffffffu, w_l, k);
            uint2 raw = reinterpret_cast<const uint2*>(h + (size_t)ss * HID)[lane];
            float2 f0 = __half22float2(*reinterpret_cast<__half2*>(&raw.x));
            float2 f1 = __half22float2(*reinterpret_cast<__half2*>(&raw.y));
            acc.x += f0.x * ww; acc.y += f0.y * ww;
            acc.z += f1.x * ww; acc.w += f1.y * ww;
        }
    }
    reinterpret_cast<float4*>(o + (size_t)warp * HID)[lane] = acc;
}

// ---------------- pipelined tf32 tensor-core GEMM ----------------------------
__device__ __forceinline__ void mma_tf32(float c[4], uint32_t a0, uint32_t a1,
                                         uint32_t a2, uint32_t a3,
                                         uint32_t b0, uint32_t b1) {
    asm volatile(
        "mma.sync.aligned.m16n8k8.row.col.f32.tf32.tf32.f32 "
        "{%0,%1,%2,%3}, {%4,%5,%6,%7}, {%8,%9}, {%0,%1,%2,%3};"
        : "+f"(c[0]), "+f"(c[1]), "+f"(c[2]), "+f"(c[3])
        : "r"(a0), "r"(a1), "r"(a2), "r"(a3), "r"(b0), "r"(b1));
}
__device__ __forceinline__ void cpasync16(uint32_t dst, const void* src, int sz) {
    asm volatile("cp.async.cg.shared.global [%0], [%1], 16, %2;"
                 :: "r"(dst), "l"(src), "r"(sz));
}
__device__ __forceinline__ void cp_commit() { asm volatile("cp.async.commit_group;"); }
__device__ __forceinline__ void cp_wait0()  { asm volatile("cp.async.wait_group 0;"); }

#define APAD 36
#define A_WORDS (2 * 128 * APAD)
#define BPAD(BN) ((BN) + 8)
#define B_WORDS(BN) (2 * 32 * BPAD(BN))
#define GEMM_SMEM(BN) ((A_WORDS + B_WORDS(BN)) * 4)

// OUT_HALF: C is __half* (pure h = A@B, no bias). else float* (+bias if BIAS).
template<bool RELU_A, bool BIAS, bool OUT_HALF, int BN>
__global__ __launch_bounds__(256)
void tf32gemm(const float* __restrict__ A,
              const float* __restrict__ B,
              void* __restrict__ Cv,
              const float* __restrict__ bias,
              int M, int N, int K, int ldb) {
    const int BM = 128, BK = 32;
    const int NT = BN / 16;
    extern __shared__ __align__(16) uint32_t smem[];
    uint32_t (*As)[BM][APAD] = reinterpret_cast<uint32_t (*)[BM][APAD]>(smem);
    uint32_t (*Bs)[BK][BPAD(BN)] =
        reinterpret_cast<uint32_t (*)[BK][BPAD(BN)]>(smem + A_WORDS);

    int tid  = threadIdx.x;
    int lane = tid & 31;
    int wid  = tid >> 5;
    int gid  = lane >> 2;
    int tig  = lane & 3;
    int wm   = (wid & 3) * 32;
    int wn   = (wid >> 2) * (BN / 2);

    int row0 = blockIdx.y * BM;
    int col0 = blockIdx.x * BN;

    uint32_t sA = (uint32_t)__cvta_generic_to_shared(&As[0][0][0]);
    uint32_t sB = (uint32_t)__cvta_generic_to_shared(&Bs[0][0][0]);

    float acc[2][NT][4];
    #pragma unroll
    for (int mt = 0; mt < 2; mt++)
        #pragma unroll
        for (int nt = 0; nt < NT; nt++)
            #pragma unroll
            for (int r = 0; r < 4; r++) acc[mt][nt][r] = 0.f;

    int aRow = tid >> 3;
    int aC4  = (tid & 7) * 4;
    int bRow = tid / (BN / 4);
    int bC4  = (tid % (BN / 4)) * 4;
    const int BROWSTEP = 256 / (BN / 4);

    auto loadA = [&](int k0, int st) {
        #pragma unroll
        for (int i = 0; i < 4; i++) {
            int row = aRow + i * 32;
            int gr  = row0 + row;
            int grc = gr < M ? gr : M - 1;
            const float* src = A + (size_t)grc * K + k0 + aC4;
            uint32_t dst = sA + (((st * BM + row) * APAD) + aC4) * 4;
            cpasync16(dst, src, gr < M ? 16 : 0);
        }
    };
    auto loadB = [&](int k0, int st) {
        #pragma unroll
        for (int i = 0; i < 32 / BROWSTEP; i++) {
            int row = bRow + i * BROWSTEP;
            int gk  = k0 + row;
            int gc  = col0 + bC4;
            int rem = N - gc;
            int sz  = rem >= 4 ? 16 : (rem > 0 ? rem * 4 : 0);
            const float* src = B + (size_t)gk * ldb + (rem > 0 ? gc : 0);
            uint32_t dst = sB + (((st * BK + row) * BPAD(BN)) + bC4) * 4;
            cpasync16(dst, src, sz);
        }
    };

    int KT = K / BK;
    loadA(0, 0); loadB(0, 0);
    cp_commit();

    for (int kt = 0; kt < KT; kt++) {
        cp_wait0();
        __syncthreads();
        if (kt + 1 < KT) {
            loadA((kt + 1) * BK, (kt + 1) & 1);
            loadB((kt + 1) * BK, (kt + 1) & 1);
            cp_commit();
        }
        int st = kt & 1;
        #pragma unroll
        for (int kc = 0; kc < 4; kc++) {
            int ks = kc * 8;
            uint32_t a[2][4];
            #pragma unroll
            for (int mt = 0; mt < 2; mt++) {
                int r = wm + mt * 16 + gid;
                if (RELU_A) {
                    a[mt][0] = __float_as_uint(fmaxf(__uint_as_float(As[st][r    ][ks + tig    ]), 0.f));
                    a[mt][1] = __float_as_uint(fmaxf(__uint_as_float(As[st][r + 8][ks + tig    ]), 0.f));
                    a[mt][2] = __float_as_uint(fmaxf(__uint_as_float(As[st][r    ][ks + tig + 4]), 0.f));
                    a[mt][3] = __float_as_uint(fmaxf(__uint_as_float(As[st][r + 8][ks + tig + 4]), 0.f));
                } else {
                    a[mt][0] = As[st][r    ][ks + tig    ];
                    a[mt][1] = As[st][r + 8][ks + tig    ];
                    a[mt][2] = As[st][r    ][ks + tig + 4];
                    a[mt][3] = As[st][r + 8][ks + tig + 4];
                }
            }
            uint32_t b[NT][2];
            #pragma unroll
            for (int nt = 0; nt < NT; nt++) {
                int c = wn + nt * 8 + gid;
                b[nt][0] = Bs[st][ks + tig    ][c];
                b[nt][1] = Bs[st][ks + tig + 4][c];
            }
            #pragma unroll
            for (int mt = 0; mt < 2; mt++)
                #pragma unroll
                for (int nt = 0; nt < NT; nt++)
                    mma_tf32(acc[mt][nt], a[mt][0], a[mt][1], a[mt][2], a[mt][3],
                             b[nt][0], b[nt][1]);
        }
        __syncthreads();
    }

    #pragma unroll
    for (int mt = 0; mt < 2; mt++) {
        #pragma unroll
        for (int rr = 0; rr < 2; rr++) {
            int gr = row0 + wm + mt * 16 + gid + rr * 8;
            if (gr >= M) continue;
            #pragma unroll
            for (int nt = 0; nt < NT; nt++) {
                int gc = col0 + wn + nt * 8 + tig * 2;
                float v0 = acc[mt][nt][rr * 2 + 0];
                float v1 = acc[mt][nt][rr * 2 + 1];
                if (OUT_HALF) {
                    __half* Ch = (__half*)Cv;   // N=128: pair always in-bounds
                    *reinterpret_cast<__half2*>(Ch + (size_t)gr * N + gc) =
                        __floats2half2_rn(v0, v1);
                } else {
                    float* Cf = (float*)Cv;
                    if (gc + 1 < N) {
                        float* cp = Cf + (size_t)gr * N + gc;
                        if (BIAS) {
                            *reinterpret_cast<float2*>(cp) =
                                make_float2(v0 + bias[gc], v1 + bias[gc + 1]);
                        } else {
                            *reinterpret_cast<float2*>(cp) = make_float2(v0, v1);
                        }
                    } else if (gc < N) {
                        Cf[(size_t)gr * N + gc] = BIAS ? v0 + bias[gc] : v0;
                    }
                }
            }
        }
    }
}

// ---------------- launch ------------------------------------------------------
extern "C" void kernel_launch(void* const* d_in, const int* in_sizes, int n_in,
                              void* d_out, int out_size) {
    const float* x    = (const float*)d_in[0];
    const int*   ei   = (const int*)d_in[1];
    const float* text = (const float*)d_in[2];
    const float* W1   = (const float*)d_in[3];
    const float* b1   = (const float*)d_in[4];
    const float* W2   = (const float*)d_in[5];
    const float* b2   = (const float*)d_in[6];
    const float* Wc   = (const float*)d_in[7];
    const float* bc   = (const float*)d_in[8];
    float* out = (float*)d_out;

    float *deg, *o1, *o2, *tv, *ew;
    __half *h1, *h2;
    int *ecnt, *offs, *cursor, *esrc, *counter;
    cudaGetSymbolAddress((void**)&deg,    g_deg);
    cudaGetSymbolAddress((void**)&h1,     g_h1);
    cudaGetSymbolAddress((void**)&o1,     g_o1);
    cudaGetSymbolAddress((void**)&h2,     g_h2);
    cudaGetSymbolAddress((void**)&o2,     g_o2);
    cudaGetSymbolAddress((void**)&tv,     g_tvec);
    cudaGetSymbolAddress((void**)&ecnt,   g_ecnt);
    cudaGetSymbolAddress((void**)&offs,   g_offs);
    cudaGetSymbolAddress((void**)&cursor, g_cursor);
    cudaGetSymbolAddress((void**)&esrc,   g_esrc);
    cudaGetSymbolAddress((void**)&ew,     g_ew);
    cudaGetSymbolAddress((void**)&counter,g_counter);

    cudaFuncSetAttribute(tf32gemm<false, false, true, 64>,
                         cudaFuncAttributeMaxDynamicSharedMemorySize, GEMM_SMEM(64));
    cudaFuncSetAttribute(tf32gemm<true, false, true, 64>,
                         cudaFuncAttributeMaxDynamicSharedMemorySize, GEMM_SMEM(64));
    cudaFuncSetAttribute(tf32gemm<false, true, false, 128>,
                         cudaFuncAttributeMaxDynamicSharedMemorySize, GEMM_SMEM(128));

    const int* srcp = ei;
    const int* dstp = ei + NE;

    // prep (single stream, merged launches)
    init_all   <<<(NN + 255) / 256, 256>>>(deg, tv, bc, counter);
    deg_count  <<<(NE + 255) / 256, 256>>>(dstp, deg);
    rsqrt_alloc<<<(NN + 255) / 256, 256>>>(deg, ecnt, offs, cursor, counter);
    fill_edges <<<(NE + 255) / 256, 256>>>(srcp, dstp, deg, cursor, esrc, ew);
    dim3 gtp((OUTC + 127) / 128, TDIM / 128);
    text_proj_part<<<gtp, 128>>>(text, Wc, tv);

    dim3 gHid(2, (NN + 127) / 128);
    dim3 gOut((OUTC + 127) / 128, (NN + 127) / 128);
    int gatherBlocks = (NN * 32 + 255) / 256;

    // layer 1: h1(half) = x@W1 ; gather fuses bias+self+edges -> o1
    tf32gemm<false, false, true, 64><<<gHid, 256, GEMM_SMEM(64)>>>(
        x, W1, h1, nullptr, NN, HID, INC, HID);
    gather_edges<<<gatherBlocks, 256>>>(offs, ecnt, esrc, ew, h1, deg, b1, o1);

    // layer 2
    tf32gemm<true, false, true, 64><<<gHid, 256, GEMM_SMEM(64)>>>(
        o1, W2, h2, nullptr, NN, HID, HID, HID);
    gather_edges<<<gatherBlocks, 256>>>(offs, ecnt, esrc, ew, h2, deg, b2, o2);

    // classifier: out = o2 @ Wc[:128] + tvec
    tf32gemm<false, true, false, 128><<<gOut, 256, GEMM_SMEM(128)>>>(
        o2, Wc, out, tv, NN, OUTC, HID, OUTC);
}

// round 10
// speedup vs baseline: 4.1724x; 1.0746x over previous
#include <cuda_runtime.h>
#include <cuda_fp16.h>
#include <cstdint>

#define NN 50000
#define NE 800000
#define INC 256
#define HID 128
#define OUTC 1000
#define TDIM 768

// ---------------- scratch ----------------------------------------------------
__device__ __align__(256) float  g_deg[NN];
__device__ __align__(256) __half g_h1[(size_t)NN * HID];
__device__ __align__(256) float  g_o1[(size_t)NN * HID];
__device__ __align__(256) __half g_h2[(size_t)NN * HID];
__device__ __align__(256) float  g_o2[(size_t)NN * HID];
__device__ __align__(256) float  g_tvec[1024];
__device__ __align__(256) int    g_ecnt[NN];
__device__ __align__(256) int    g_offs[NN];
__device__ __align__(256) int    g_cursor[NN];
__device__ __align__(256) int    g_esrc[NE];
__device__ int g_counter;

// ---------------- prep kernels ------------------------------------------------
__global__ void init_all(float* deg, float* tvec, const float* __restrict__ bc,
                         int* counter) {
    int i = blockIdx.x * blockDim.x + threadIdx.x;
    if (i == 0) *counter = 0;
    if (i < NN) deg[i] = 1.0f;
    if (i < OUTC) tvec[i] = bc[i];
}
__global__ void deg_count(const int* __restrict__ dst, float* deg) {
    int e = blockIdx.x * blockDim.x + threadIdx.x;
    if (e < NE) atomicAdd(&deg[dst[e]], 1.0f);
}
__global__ void rsqrt_alloc(float* deg, int* ecnt, int* offs, int* cursor,
                            int* counter) {
    int i = blockIdx.x * blockDim.x + threadIdx.x;
    if (i >= NN) return;
    float d = deg[i];
    int c = (int)d - 1;
    ecnt[i] = c;
    deg[i] = rsqrtf(d);
    int base = atomicAdd(counter, c);
    offs[i] = base;
    cursor[i] = base;
}
// bucket edges by destination (weights computed later in gather from dinv)
__global__ void fill_edges(const int* __restrict__ src,
                           const int* __restrict__ dst,
                           int* __restrict__ cursor,
                           int* __restrict__ esrc) {
    int e = blockIdx.x * blockDim.x + threadIdx.x;
    if (e >= NE) return;
    int pos = atomicAdd(&cursor[dst[e]], 1);
    esrc[pos] = src[e];
}
__global__ void text_proj_part(const float* __restrict__ text,
                               const float* __restrict__ Wc,
                               float* __restrict__ tvec) {
    int o = blockIdx.x * 128 + threadIdx.x;
    int d0 = blockIdx.y * 128;
    if (o >= OUTC) return;
    float s = 0.f;
    #pragma unroll 8
    for (int d = d0; d < d0 + 128; d++)
        s += text[d] * Wc[(size_t)(HID + d) * OUTC + o];
    atomicAdd(&tvec[o], s);
}

// ---------------- CSR gather (h fp16, self+bias fused, weights on-the-fly) ---
__global__ void gather_edges(const int* __restrict__ offs,
                             const int* __restrict__ ecnt,
                             const int* __restrict__ esrc,
                             const __half* __restrict__ h,
                             const float* __restrict__ dinv,
                             const float* __restrict__ bias,
                             float* __restrict__ o) {
    int warp = (blockIdx.x * blockDim.x + threadIdx.x) >> 5;
    int lane = threadIdx.x & 31;
    if (warp >= NN) return;
    int base = offs[warp];
    int end  = base + ecnt[warp];
    float di = dinv[warp];
    float di2 = di * di;
    float4 acc = reinterpret_cast<const float4*>(bias)[lane];
    {   // self contribution
        uint2 raw = reinterpret_cast<const uint2*>(h + (size_t)warp * HID)[lane];
        float2 f0 = __half22float2(*reinterpret_cast<__half2*>(&raw.x));
        float2 f1 = __half22float2(*reinterpret_cast<__half2*>(&raw.y));
        acc.x += f0.x * di2; acc.y += f0.y * di2;
        acc.z += f1.x * di2; acc.w += f1.y * di2;
    }
    for (int j0 = base; j0 < end; j0 += 32) {
        int e = j0 + lane;
        bool ok = e < end;
        int   s_l = ok ? esrc[e] : 0;
        float w_l = ok ? dinv[s_l] * di : 0.f;
        int m = min(32, end - j0);
        #pragma unroll 4
        for (int k = 0; k < m; k++) {
            int   ss = __shfl_sync(0xffffffffu, s_l, k);
            float ww = __shfl_sync(0xffffffffu, w_l, k);
            uint2 raw = reinterpret_cast<const uint2*>(h + (size_t)ss * HID)[lane];
            float2 f0 = __half22float2(*reinterpret_cast<__half2*>(&raw.x));
            float2 f1 = __half22float2(*reinterpret_cast<__half2*>(&raw.y));
            acc.x += f0.x * ww; acc.y += f0.y * ww;
            acc.z += f1.x * ww; acc.w += f1.y * ww;
        }
    }
    reinterpret_cast<float4*>(o + (size_t)warp * HID)[lane] = acc;
}

// ---------------- pipelined tf32 tensor-core GEMM ----------------------------
__device__ __forceinline__ void mma_tf32(float c[4], uint32_t a0, uint32_t a1,
                                         uint32_t a2, uint32_t a3,
                                         uint32_t b0, uint32_t b1) {
    asm volatile(
        "mma.sync.aligned.m16n8k8.row.col.f32.tf32.tf32.f32 "
        "{%0,%1,%2,%3}, {%4,%5,%6,%7}, {%8,%9}, {%0,%1,%2,%3};"
        : "+f"(c[0]), "+f"(c[1]), "+f"(c[2]), "+f"(c[3])
        : "r"(a0), "r"(a1), "r"(a2), "r"(a3), "r"(b0), "r"(b1));
}
__device__ __forceinline__ void cpasync16(uint32_t dst, const void* src, int sz) {
    asm volatile("cp.async.cg.shared.global [%0], [%1], 16, %2;"
                 :: "r"(dst), "l"(src), "r"(sz));
}
__device__ __forceinline__ void cp_commit() { asm volatile("cp.async.commit_group;"); }
__device__ __forceinline__ void cp_wait0()  { asm volatile("cp.async.wait_group 0;"); }

#define APAD 36
#define A_WORDS (2 * 128 * APAD)
#define BPAD(BN) ((BN) + 8)
#define B_WORDS(BN) (2 * 32 * BPAD(BN))
#define GEMM_SMEM(BN) ((A_WORDS + B_WORDS(BN)) * 4)

template<bool RELU_A, bool BIAS, bool OUT_HALF, int BN>
__global__ __launch_bounds__(256)
void tf32gemm(const float* __restrict__ A,
              const float* __restrict__ B,
              void* __restrict__ Cv,
              const float* __restrict__ bias,
              int M, int N, int K, int ldb) {
    const int BM = 128, BK = 32;
    const int NT = BN / 16;
    extern __shared__ __align__(16) uint32_t smem[];
    uint32_t (*As)[BM][APAD] = reinterpret_cast<uint32_t (*)[BM][APAD]>(smem);
    uint32_t (*Bs)[BK][BPAD(BN)] =
        reinterpret_cast<uint32_t (*)[BK][BPAD(BN)]>(smem + A_WORDS);

    int tid  = threadIdx.x;
    int lane = tid & 31;
    int wid  = tid >> 5;
    int gid  = lane >> 2;
    int tig  = lane & 3;
    int wm   = (wid & 3) * 32;
    int wn   = (wid >> 2) * (BN / 2);

    int row0 = blockIdx.y * BM;
    int col0 = blockIdx.x * BN;

    uint32_t sA = (uint32_t)__cvta_generic_to_shared(&As[0][0][0]);
    uint32_t sB = (uint32_t)__cvta_generic_to_shared(&Bs[0][0][0]);

    float acc[2][NT][4];
    #pragma unroll
    for (int mt = 0; mt < 2; mt++)
        #pragma unroll
        for (int nt = 0; nt < NT; nt++)
            #pragma unroll
            for (int r = 0; r < 4; r++) acc[mt][nt][r] = 0.f;

    int aRow = tid >> 3;
    int aC4  = (tid & 7) * 4;
    int bRow = tid / (BN / 4);
    int bC4  = (tid % (BN / 4)) * 4;
    const int BROWSTEP = 256 / (BN / 4);

    auto loadA = [&](int k0, int st) {
        #pragma unroll
        for (int i = 0; i < 4; i++) {
            int row = aRow + i * 32;
            int gr  = row0 + row;
            int grc = gr < M ? gr : M - 1;
            const float* src = A + (size_t)grc * K + k0 + aC4;
            uint32_t dst = sA + (((st * BM + row) * APAD) + aC4) * 4;
            cpasync16(dst, src, gr < M ? 16 : 0);
        }
    };
    auto loadB = [&](int k0, int st) {
        #pragma unroll
        for (int i = 0; i < 32 / BROWSTEP; i++) {
            int row = bRow + i * BROWSTEP;
            int gk  = k0 + row;
            int gc  = col0 + bC4;
            int rem = N - gc;
            int sz  = rem >= 4 ? 16 : (rem > 0 ? rem * 4 : 0);
            const float* src = B + (size_t)gk * ldb + (rem > 0 ? gc : 0);
            uint32_t dst = sB + (((st * BK + row) * BPAD(BN)) + bC4) * 4;
            cpasync16(dst, src, sz);
        }
    };

    int KT = K / BK;
    loadA(0, 0); loadB(0, 0);
    cp_commit();

    for (int kt = 0; kt < KT; kt++) {
        cp_wait0();
        __syncthreads();
        if (kt + 1 < KT) {
            loadA((kt + 1) * BK, (kt + 1) & 1);
            loadB((kt + 1) * BK, (kt + 1) & 1);
            cp_commit();
        }
        int st = kt & 1;
        #pragma unroll
        for (int kc = 0; kc < 4; kc++) {
            int ks = kc * 8;
            uint32_t a[2][4];
            #pragma unroll
            for (int mt = 0; mt < 2; mt++) {
                int r = wm + mt * 16 + gid;
                if (RELU_A) {
                    a[mt][0] = __float_as_uint(fmaxf(__uint_as_float(As[st][r    ][ks + tig    ]), 0.f));
                    a[mt][1] = __float_as_uint(fmaxf(__uint_as_float(As[st][r + 8][ks + tig    ]), 0.f));
                    a[mt][2] = __float_as_uint(fmaxf(__uint_as_float(As[st][r    ][ks + tig + 4]), 0.f));
                    a[mt][3] = __float_as_uint(fmaxf(__uint_as_float(As[st][r + 8][ks + tig + 4]), 0.f));
                } else {
                    a[mt][0] = As[st][r    ][ks + tig    ];
                    a[mt][1] = As[st][r + 8][ks + tig    ];
                    a[mt][2] = As[st][r    ][ks + tig + 4];
                    a[mt][3] = As[st][r + 8][ks + tig + 4];
                }
            }
            uint32_t b[NT][2];
            #pragma unroll
            for (int nt = 0; nt < NT; nt++) {
                int c = wn + nt * 8 + gid;
                b[nt][0] = Bs[st][ks + tig    ][c];
                b[nt][1] = Bs[st][ks + tig + 4][c];
            }
            #pragma unroll
            for (int mt = 0; mt < 2; mt++)
                #pragma unroll
                for (int nt = 0; nt < NT; nt++)
                    mma_tf32(acc[mt][nt], a[mt][0], a[mt][1], a[mt][2], a[mt][3],
                             b[nt][0], b[nt][1]);
        }
        __syncthreads();
    }

    #pragma unroll
    for (int mt = 0; mt < 2; mt++) {
        #pragma unroll
        for (int rr = 0; rr < 2; rr++) {
            int gr = row0 + wm + mt * 16 + gid + rr * 8;
            if (gr >= M) continue;
            #pragma unroll
            for (int nt = 0; nt < NT; nt++) {
                int gc = col0 + wn + nt * 8 + tig * 2;
                float v0 = acc[mt][nt][rr * 2 + 0];
                float v1 = acc[mt][nt][rr * 2 + 1];
                if (OUT_HALF) {
                    __half* Ch = (__half*)Cv;
                    *reinterpret_cast<__half2*>(Ch + (size_t)gr * N + gc) =
                        __floats2half2_rn(v0, v1);
                } else {
                    float* Cf = (float*)Cv;
                    if (gc + 1 < N) {
                        float* cp = Cf + (size_t)gr * N + gc;
                        if (BIAS) {
                            *reinterpret_cast<float2*>(cp) =
                                make_float2(v0 + bias[gc], v1 + bias[gc + 1]);
                        } else {
                            *reinterpret_cast<float2*>(cp) = make_float2(v0, v1);
                        }
                    } else if (gc < N) {
                        Cf[(size_t)gr * N + gc] = BIAS ? v0 + bias[gc] : v0;
                    }
                }
            }
        }
    }
}

// ---------------- launch ------------------------------------------------------
extern "C" void kernel_launch(void* const* d_in, const int* in_sizes, int n_in,
                              void* d_out, int out_size) {
    const float* x    = (const float*)d_in[0];
    const int*   ei   = (const int*)d_in[1];
    const float* text = (const float*)d_in[2];
    const float* W1   = (const float*)d_in[3];
    const float* b1   = (const float*)d_in[4];
    const float* W2   = (const float*)d_in[5];
    const float* b2   = (const float*)d_in[6];
    const float* Wc   = (const float*)d_in[7];
    const float* bc   = (const float*)d_in[8];
    float* out = (float*)d_out;

    float *deg, *o1, *o2, *tv;
    __half *h1, *h2;
    int *ecnt, *offs, *cursor, *esrc, *counter;
    cudaGetSymbolAddress((void**)&deg,    g_deg);
    cudaGetSymbolAddress((void**)&h1,     g_h1);
    cudaGetSymbolAddress((void**)&o1,     g_o1);
    cudaGetSymbolAddress((void**)&h2,     g_h2);
    cudaGetSymbolAddress((void**)&o2,     g_o2);
    cudaGetSymbolAddress((void**)&tv,     g_tvec);
    cudaGetSymbolAddress((void**)&ecnt,   g_ecnt);
    cudaGetSymbolAddress((void**)&offs,   g_offs);
    cudaGetSymbolAddress((void**)&cursor, g_cursor);
    cudaGetSymbolAddress((void**)&esrc,   g_esrc);
    cudaGetSymbolAddress((void**)&counter,g_counter);

    cudaFuncSetAttribute(tf32gemm<false, false, true, 64>,
                         cudaFuncAttributeMaxDynamicSharedMemorySize, GEMM_SMEM(64));
    cudaFuncSetAttribute(tf32gemm<true, false, true, 64>,
                         cudaFuncAttributeMaxDynamicSharedMemorySize, GEMM_SMEM(64));
    cudaFuncSetAttribute(tf32gemm<false, true, false, 128>,
                         cudaFuncAttributeMaxDynamicSharedMemorySize, GEMM_SMEM(128));

    const int* srcp = ei;
    const int* dstp = ei + NE;

    // fork: prep chain on side stream, GEMM1 on main stream (capture-safe
    // fork/join: side stream enters capture via eFork wait, rejoins via
    // eCSR/eTxt waits on the main stream before any dependent work).
    cudaStream_t s2;
    cudaStreamCreateWithFlags(&s2, cudaStreamNonBlocking);
    cudaEvent_t eFork, eCSR, eTxt;
    cudaEventCreateWithFlags(&eFork, cudaEventDisableTiming);
    cudaEventCreateWithFlags(&eCSR,  cudaEventDisableTiming);
    cudaEventCreateWithFlags(&eTxt,  cudaEventDisableTiming);

    cudaEventRecord(eFork, 0);
    cudaStreamWaitEvent(s2, eFork, 0);

    init_all   <<<(NN + 255) / 256, 256, 0, s2>>>(deg, tv, bc, counter);
    deg_count  <<<(NE + 255) / 256, 256, 0, s2>>>(dstp, deg);
    rsqrt_alloc<<<(NN + 255) / 256, 256, 0, s2>>>(deg, ecnt, offs, cursor, counter);
    fill_edges <<<(NE + 255) / 256, 256, 0, s2>>>(srcp, dstp, cursor, esrc);
    cudaEventRecord(eCSR, s2);
    dim3 gtp((OUTC + 127) / 128, TDIM / 128);
    text_proj_part<<<gtp, 128, 0, s2>>>(text, Wc, tv);
    cudaEventRecord(eTxt, s2);

    dim3 gHid(2, (NN + 127) / 128);
    dim3 gOut((OUTC + 127) / 128, (NN + 127) / 128);
    int gatherBlocks = (NN * 32 + 255) / 256;

    // main: GEMM1 (independent of prep)
    tf32gemm<false, false, true, 64><<<gHid, 256, GEMM_SMEM(64)>>>(
        x, W1, h1, nullptr, NN, HID, INC, HID);

    // join CSR, gather1
    cudaStreamWaitEvent(0, eCSR, 0);
    gather_edges<<<gatherBlocks, 256>>>(offs, ecnt, esrc, h1, deg, b1, o1);

    // layer 2
    tf32gemm<true, false, true, 64><<<gHid, 256, GEMM_SMEM(64)>>>(
        o1, W2, h2, nullptr, NN, HID, HID, HID);
    gather_edges<<<gatherBlocks, 256>>>(offs, ecnt, esrc, h2, deg, b2, o2);

    // classifier (join text)
    cudaStreamWaitEvent(0, eTxt, 0);
    tf32gemm<false, true, false, 128><<<gOut, 256, GEMM_SMEM(128)>>>(
        o2, Wc, out, tv, NN, OUTC, HID, OUTC);
}

// round 11
// speedup vs baseline: 4.2079x; 1.0085x over previous
#include <cuda_runtime.h>
#include <cuda_fp16.h>
#include <cstdint>

#define NN 50000
#define NE 800000
#define INC 256
#define HID 128
#define OUTC 1000
#define TDIM 768

// ---------------- scratch ----------------------------------------------------
__device__ __align__(256) float  g_deg[NN];
__device__ __align__(256) __half g_h1[(size_t)NN * HID];
__device__ __align__(256) float  g_o1[(size_t)NN * HID];
__device__ __align__(256) __half g_h2[(size_t)NN * HID];
__device__ __align__(256) float  g_o2[(size_t)NN * HID];
__device__ __align__(256) float  g_tvec[1024];
__device__ __align__(256) int    g_ecnt[NN];
__device__ __align__(256) int    g_offs[NN];
__device__ __align__(256) int    g_cursor[NN];
__device__ __align__(256) int    g_esrc[NE];
__device__ int g_counter;

// ---------------- prep kernels ------------------------------------------------
__global__ void init_all(float* deg, float* tvec, const float* __restrict__ bc,
                         int* counter) {
    int i = blockIdx.x * blockDim.x + threadIdx.x;
    if (i == 0) *counter = 0;
    if (i < NN) deg[i] = 1.0f;
    if (i < OUTC) tvec[i] = bc[i];
}
// 4 edges per thread (int4 loads) -> MLP=4 on the atomic chain
__global__ void deg_count4(const int* __restrict__ dst, float* deg) {
    int t = blockIdx.x * blockDim.x + threadIdx.x;
    if (t >= NE / 4) return;
    int4 d = reinterpret_cast<const int4*>(dst)[t];
    atomicAdd(&deg[d.x], 1.0f);
    atomicAdd(&deg[d.y], 1.0f);
    atomicAdd(&deg[d.z], 1.0f);
    atomicAdd(&deg[d.w], 1.0f);
}
__global__ void rsqrt_alloc(float* deg, int* ecnt, int* offs, int* cursor,
                            int* counter) {
    int i = blockIdx.x * blockDim.x + threadIdx.x;
    if (i >= NN) return;
    float d = deg[i];
    int c = (int)d - 1;
    ecnt[i] = c;
    deg[i] = rsqrtf(d);
    int base = atomicAdd(counter, c);
    offs[i] = base;
    cursor[i] = base;
}
// 4 edges per thread bucket fill
__global__ void fill_edges4(const int* __restrict__ src,
                            const int* __restrict__ dst,
                            int* __restrict__ cursor,
                            int* __restrict__ esrc) {
    int t = blockIdx.x * blockDim.x + threadIdx.x;
    if (t >= NE / 4) return;
    int4 s = reinterpret_cast<const int4*>(src)[t];
    int4 d = reinterpret_cast<const int4*>(dst)[t];
    int p0 = atomicAdd(&cursor[d.x], 1);
    int p1 = atomicAdd(&cursor[d.y], 1);
    int p2 = atomicAdd(&cursor[d.z], 1);
    int p3 = atomicAdd(&cursor[d.w], 1);
    esrc[p0] = s.x;
    esrc[p1] = s.y;
    esrc[p2] = s.z;
    esrc[p3] = s.w;
}
__global__ void text_proj_part(const float* __restrict__ text,
                               const float* __restrict__ Wc,
                               float* __restrict__ tvec) {
    int o = blockIdx.x * 128 + threadIdx.x;
    int d0 = blockIdx.y * 128;
    if (o >= OUTC) return;
    float s = 0.f;
    #pragma unroll 8
    for (int d = d0; d < d0 + 128; d++)
        s += text[d] * Wc[(size_t)(HID + d) * OUTC + o];
    atomicAdd(&tvec[o], s);
}

// ---------------- CSR gather (h fp16, self+bias fused, weights on-the-fly) ---
__global__ void gather_edges(const int* __restrict__ offs,
                             const int* __restrict__ ecnt,
                             const int* __restrict__ esrc,
                             const __half* __restrict__ h,
                             const float* __restrict__ dinv,
                             const float* __restrict__ bias,
                             float* __restrict__ o) {
    int warp = (blockIdx.x * blockDim.x + threadIdx.x) >> 5;
    int lane = threadIdx.x & 31;
    if (warp >= NN) return;
    int base = offs[warp];
    int end  = base + ecnt[warp];
    float di = dinv[warp];
    float di2 = di * di;
    float4 acc = reinterpret_cast<const float4*>(bias)[lane];
    {   // self contribution
        uint2 raw = reinterpret_cast<const uint2*>(h + (size_t)warp * HID)[lane];
        float2 f0 = __half22float2(*reinterpret_cast<__half2*>(&raw.x));
        float2 f1 = __half22float2(*reinterpret_cast<__half2*>(&raw.y));
        acc.x += f0.x * di2; acc.y += f0.y * di2;
        acc.z += f1.x * di2; acc.w += f1.y * di2;
    }
    for (int j0 = base; j0 < end; j0 += 32) {
        int e = j0 + lane;
        bool ok = e < end;
        int   s_l = ok ? esrc[e] : 0;
        float w_l = ok ? dinv[s_l] * di : 0.f;
        int m = min(32, end - j0);
        #pragma unroll 8
        for (int k = 0; k < m; k++) {
            int   ss = __shfl_sync(0xffffffffu, s_l, k);
            float ww = __shfl_sync(0xffffffffu, w_l, k);
            uint2 raw = reinterpret_cast<const uint2*>(h + (size_t)ss * HID)[lane];
            float2 f0 = __half22float2(*reinterpret_cast<__half2*>(&raw.x));
            float2 f1 = __half22float2(*reinterpret_cast<__half2*>(&raw.y));
            acc.x += f0.x * ww; acc.y += f0.y * ww;
            acc.z += f1.x * ww; acc.w += f1.y * ww;
        }
    }
    reinterpret_cast<float4*>(o + (size_t)warp * HID)[lane] = acc;
}

// ---------------- pipelined tf32 tensor-core GEMM ----------------------------
__device__ __forceinline__ void mma_tf32(float c[4], uint32_t a0, uint32_t a1,
                                         uint32_t a2, uint32_t a3,
                                         uint32_t b0, uint32_t b1) {
    asm volatile(
        "mma.sync.aligned.m16n8k8.row.col.f32.tf32.tf32.f32 "
        "{%0,%1,%2,%3}, {%4,%5,%6,%7}, {%8,%9}, {%0,%1,%2,%3};"
        : "+f"(c[0]), "+f"(c[1]), "+f"(c[2]), "+f"(c[3])
        : "r"(a0), "r"(a1), "r"(a2), "r"(a3), "r"(b0), "r"(b1));
}
__device__ __forceinline__ void cpasync16(uint32_t dst, const void* src, int sz) {
    asm volatile("cp.async.cg.shared.global [%0], [%1], 16, %2;"
                 :: "r"(dst), "l"(src), "r"(sz));
}
__device__ __forceinline__ void cp_commit() { asm volatile("cp.async.commit_group;"); }
__device__ __forceinline__ void cp_wait0()  { asm volatile("cp.async.wait_group 0;"); }

#define APAD 36
#define A_WORDS (2 * 128 * APAD)
#define BPAD(BN) ((BN) + 8)
#define B_WORDS(BN) (2 * 32 * BPAD(BN))
#define GEMM_SMEM(BN) ((A_WORDS + B_WORDS(BN)) * 4)

template<bool RELU_A, bool BIAS, bool OUT_HALF, int BN>
__global__ __launch_bounds__(256)
void tf32gemm(const float* __restrict__ A,
              const float* __restrict__ B,
              void* __restrict__ Cv,
              const float* __restrict__ bias,
              int M, int N, int K, int ldb) {
    const int BM = 128, BK = 32;
    const int NT = BN / 16;
    extern __shared__ __align__(16) uint32_t smem[];
    uint32_t (*As)[BM][APAD] = reinterpret_cast<uint32_t (*)[BM][APAD]>(smem);
    uint32_t (*Bs)[BK][BPAD(BN)] =
        reinterpret_cast<uint32_t (*)[BK][BPAD(BN)]>(smem + A_WORDS);

    int tid  = threadIdx.x;
    int lane = tid & 31;
    int wid  = tid >> 5;
    int gid  = lane >> 2;
    int tig  = lane & 3;
    int wm   = (wid & 3) * 32;
    int wn   = (wid >> 2) * (BN / 2);

    int row0 = blockIdx.y * BM;
    int col0 = blockIdx.x * BN;

    uint32_t sA = (uint32_t)__cvta_generic_to_shared(&As[0][0][0]);
    uint32_t sB = (uint32_t)__cvta_generic_to_shared(&Bs[0][0][0]);

    float acc[2][NT][4];
    #pragma unroll
    for (int mt = 0; mt < 2; mt++)
        #pragma unroll
        for (int nt = 0; nt < NT; nt++)
            #pragma unroll
            for (int r = 0; r < 4; r++) acc[mt][nt][r] = 0.f;

    int aRow = tid >> 3;
    int aC4  = (tid & 7) * 4;
    int bRow = tid / (BN / 4);
    int bC4  = (tid % (BN / 4)) * 4;
    const int BROWSTEP = 256 / (BN / 4);

    auto loadA = [&](int k0, int st) {
        #pragma unroll
        for (int i = 0; i < 4; i++) {
            int row = aRow + i * 32;
            int gr  = row0 + row;
            int grc = gr < M ? gr : M - 1;
            const float* src = A + (size_t)grc * K + k0 + aC4;
            uint32_t dst = sA + (((st * BM + row) * APAD) + aC4) * 4;
            cpasync16(dst, src, gr < M ? 16 : 0);
        }
    };
    auto loadB = [&](int k0, int st) {
        #pragma unroll
        for (int i = 0; i < 32 / BROWSTEP; i++) {
            int row = bRow + i * BROWSTEP;
            int gk  = k0 + row;
            int gc  = col0 + bC4;
            int rem = N - gc;
            int sz  = rem >= 4 ? 16 : (rem > 0 ? rem * 4 : 0);
            const float* src = B + (size_t)gk * ldb + (rem > 0 ? gc : 0);
            uint32_t dst = sB + (((st * BK + row) * BPAD(BN)) + bC4) * 4;
            cpasync16(dst, src, sz);
        }
    };

    int KT = K / BK;
    loadA(0, 0); loadB(0, 0);
    cp_commit();

    for (int kt = 0; kt < KT; kt++) {
        cp_wait0();
        __syncthreads();
        if (kt + 1 < KT) {
            loadA((kt + 1) * BK, (kt + 1) & 1);
            loadB((kt + 1) * BK, (kt + 1) & 1);
            cp_commit();
        }
        int st = kt & 1;
        #pragma unroll
        for (int kc = 0; kc < 4; kc++) {
            int ks = kc * 8;
            uint32_t a[2][4];
            #pragma unroll
            for (int mt = 0; mt < 2; mt++) {
                int r = wm + mt * 16 + gid;
                if (RELU_A) {
                    a[mt][0] = __float_as_uint(fmaxf(__uint_as_float(As[st][r    ][ks + tig    ]), 0.f));
                    a[mt][1] = __float_as_uint(fmaxf(__uint_as_float(As[st][r + 8][ks + tig    ]), 0.f));
                    a[mt][2] = __float_as_uint(fmaxf(__uint_as_float(As[st][r    ][ks + tig + 4]), 0.f));
                    a[mt][3] = __float_as_uint(fmaxf(__uint_as_float(As[st][r + 8][ks + tig + 4]), 0.f));
                } else {
                    a[mt][0] = As[st][r    ][ks + tig    ];
                    a[mt][1] = As[st][r + 8][ks + tig    ];
                    a[mt][2] = As[st][r    ][ks + tig + 4];
                    a[mt][3] = As[st][r + 8][ks + tig + 4];
                }
            }
            uint32_t b[NT][2];
            #pragma unroll
            for (int nt = 0; nt < NT; nt++) {
                int c = wn + nt * 8 + gid;
                b[nt][0] = Bs[st][ks + tig    ][c];
                b[nt][1] = Bs[st][ks + tig + 4][c];
            }
            #pragma unroll
            for (int mt = 0; mt < 2; mt++)
                #pragma unroll
                for (int nt = 0; nt < NT; nt++)
                    mma_tf32(acc[mt][nt], a[mt][0], a[mt][1], a[mt][2], a[mt][3],
                             b[nt][0], b[nt][1]);
        }
        __syncthreads();
    }

    #pragma unroll
    for (int mt = 0; mt < 2; mt++) {
        #pragma unroll
        for (int rr = 0; rr < 2; rr++) {
            int gr = row0 + wm + mt * 16 + gid + rr * 8;
            if (gr >= M) continue;
            #pragma unroll
            for (int nt = 0; nt < NT; nt++) {
                int gc = col0 + wn + nt * 8 + tig * 2;
                float v0 = acc[mt][nt][rr * 2 + 0];
                float v1 = acc[mt][nt][rr * 2 + 1];
                if (OUT_HALF) {
                    __half* Ch = (__half*)Cv;
                    *reinterpret_cast<__half2*>(Ch + (size_t)gr * N + gc) =
                        __floats2half2_rn(v0, v1);
                } else {
                    float* Cf = (float*)Cv;
                    if (gc + 1 < N) {
                        float* cp = Cf + (size_t)gr * N + gc;
                        if (BIAS) {
                            *reinterpret_cast<float2*>(cp) =
                                make_float2(v0 + bias[gc], v1 + bias[gc + 1]);
                        } else {
                            *reinterpret_cast<float2*>(cp) = make_float2(v0, v1);
                        }
                    } else if (gc < N) {
                        Cf[(size_t)gr * N + gc] = BIAS ? v0 + bias[gc] : v0;
                    }
                }
            }
        }
    }
}

// ---------------- launch ------------------------------------------------------
extern "C" void kernel_launch(void* const* d_in, const int* in_sizes, int n_in,
                              void* d_out, int out_size) {
    const float* x    = (const float*)d_in[0];
    const int*   ei   = (const int*)d_in[1];
    const float* text = (const float*)d_in[2];
    const float* W1   = (const float*)d_in[3];
    const float* b1   = (const float*)d_in[4];
    const float* W2   = (const float*)d_in[5];
    const float* b2   = (const float*)d_in[6];
    const float* Wc   = (const float*)d_in[7];
    const float* bc   = (const float*)d_in[8];
    float* out = (float*)d_out;

    float *deg, *o1, *o2, *tv;
    __half *h1, *h2;
    int *ecnt, *offs, *cursor, *esrc, *counter;
    cudaGetSymbolAddress((void**)&deg,    g_deg);
    cudaGetSymbolAddress((void**)&h1,     g_h1);
    cudaGetSymbolAddress((void**)&o1,     g_o1);
    cudaGetSymbolAddress((void**)&h2,     g_h2);
    cudaGetSymbolAddress((void**)&o2,     g_o2);
    cudaGetSymbolAddress((void**)&tv,     g_tvec);
    cudaGetSymbolAddress((void**)&ecnt,   g_ecnt);
    cudaGetSymbolAddress((void**)&offs,   g_offs);
    cudaGetSymbolAddress((void**)&cursor, g_cursor);
    cudaGetSymbolAddress((void**)&esrc,   g_esrc);
    cudaGetSymbolAddress((void**)&counter,g_counter);

    cudaFuncSetAttribute(tf32gemm<false, false, true, 64>,
                         cudaFuncAttributeMaxDynamicSharedMemorySize, GEMM_SMEM(64));
    cudaFuncSetAttribute(tf32gemm<true, false, true, 64>,
                         cudaFuncAttributeMaxDynamicSharedMemorySize, GEMM_SMEM(64));
    cudaFuncSetAttribute(tf32gemm<false, true, false, 128>,
                         cudaFuncAttributeMaxDynamicSharedMemorySize, GEMM_SMEM(128));

    const int* srcp = ei;
    const int* dstp = ei + NE;

    // fork: prep chain on side stream, GEMM1 on main stream
    cudaStream_t s2;
    cudaStreamCreateWithFlags(&s2, cudaStreamNonBlocking);
    cudaEvent_t eFork, eCSR, eTxt;
    cudaEventCreateWithFlags(&eFork, cudaEventDisableTiming);
    cudaEventCreateWithFlags(&eCSR,  cudaEventDisableTiming);
    cudaEventCreateWithFlags(&eTxt,  cudaEventDisableTiming);

    cudaEventRecord(eFork, 0);
    cudaStreamWaitEvent(s2, eFork, 0);

    init_all   <<<(NN + 255) / 256, 256, 0, s2>>>(deg, tv, bc, counter);
    deg_count4 <<<(NE / 4 + 255) / 256, 256, 0, s2>>>(dstp, deg);
    rsqrt_alloc<<<(NN + 255) / 256, 256, 0, s2>>>(deg, ecnt, offs, cursor, counter);
    fill_edges4<<<(NE / 4 + 255) / 256, 256, 0, s2>>>(srcp, dstp, cursor, esrc);
    cudaEventRecord(eCSR, s2);
    dim3 gtp((OUTC + 127) / 128, TDIM / 128);
    text_proj_part<<<gtp, 128, 0, s2>>>(text, Wc, tv);
    cudaEventRecord(eTxt, s2);

    dim3 gHid(2, (NN + 127) / 128);
    dim3 gOut((OUTC + 127) / 128, (NN + 127) / 128);
    int gatherBlocks = (NN * 32 + 255) / 256;

    // main: GEMM1 (independent of prep)
    tf32gemm<false, false, true, 64><<<gHid, 256, GEMM_SMEM(64)>>>(
        x, W1, h1, nullptr, NN, HID, INC, HID);

    // join CSR, gather1
    cudaStreamWaitEvent(0, eCSR, 0);
    gather_edges<<<gatherBlocks, 256>>>(offs, ecnt, esrc, h1, deg, b1, o1);

    // layer 2
    tf32gemm<true, false, true, 64><<<gHid, 256, GEMM_SMEM(64)>>>(
        o1, W2, h2, nullptr, NN, HID, HID, HID);
    gather_edges<<<gatherBlocks, 256>>>(offs, ecnt, esrc, h2, deg, b2, o2);

    // classifier (join text)
    cudaStreamWaitEvent(0, eTxt, 0);
    tf32gemm<false, true, false, 128><<<gOut, 256, GEMM_SMEM(128)>>>(
        o2, Wc, out, tv, NN, OUTC, HID, OUTC);
}

// round 12
// speedup vs baseline: 4.4770x; 1.0639x over previous
#include <cuda_runtime.h>
#include <cuda_fp16.h>
#include <cstdint>

#define NN 50000
#define NE 800000
#define INC 256
#define HID 128
#define OUTC 1000
#define TDIM 768

// ---------------- scratch ----------------------------------------------------
__device__ __align__(256) float  g_deg[NN];
__device__ __align__(256) __half g_h1[(size_t)NN * HID];
__device__ __align__(256) __half g_o1[(size_t)NN * HID];
__device__ __align__(256) __half g_h2[(size_t)NN * HID];
__device__ __align__(256) __half g_o2[(size_t)NN * HID];
__device__ __align__(256) float  g_tvec[1024];
__device__ __align__(256) int    g_ecnt[NN];
__device__ __align__(256) int    g_offs[NN];
__device__ __align__(256) int    g_cursor[NN];
__device__ __align__(256) int    g_esrc[NE];
__device__ int g_counter;

// ---------------- prep kernels ------------------------------------------------
__global__ void init_all(float* deg, float* tvec, const float* __restrict__ bc,
                         int* counter) {
    int i = blockIdx.x * blockDim.x + threadIdx.x;
    if (i == 0) *counter = 0;
    if (i < NN) deg[i] = 1.0f;
    if (i < OUTC) tvec[i] = bc[i];
}
__global__ void deg_count(const int* __restrict__ dst, float* deg) {
    int e = blockIdx.x * blockDim.x + threadIdx.x;
    if (e < NE) atomicAdd(&deg[dst[e]], 1.0f);
}
__global__ void rsqrt_alloc(float* deg, int* ecnt, int* offs, int* cursor,
                            int* counter) {
    int i = blockIdx.x * blockDim.x + threadIdx.x;
    if (i >= NN) return;
    float d = deg[i];
    int c = (int)d - 1;
    ecnt[i] = c;
    deg[i] = rsqrtf(d);
    int base = atomicAdd(counter, c);
    offs[i] = base;
    cursor[i] = base;
}
__global__ void fill_edges(const int* __restrict__ src,
                           const int* __restrict__ dst,
                           int* __restrict__ cursor,
                           int* __restrict__ esrc) {
    int e = blockIdx.x * blockDim.x + threadIdx.x;
    if (e >= NE) return;
    int pos = atomicAdd(&cursor[dst[e]], 1);
    esrc[pos] = src[e];
}
__global__ void text_proj_part(const float* __restrict__ text,
                               const float* __restrict__ Wc,
                               float* __restrict__ tvec) {
    int o = blockIdx.x * 128 + threadIdx.x;
    int d0 = blockIdx.y * 128;
    if (o >= OUTC) return;
    float s = 0.f;
    #pragma unroll 8
    for (int d = d0; d < d0 + 128; d++)
        s += text[d] * Wc[(size_t)(HID + d) * OUTC + o];
    atomicAdd(&tvec[o], s);
}

// ---------------- CSR gather (h fp16 in, o fp16 out, fp32 accumulation) ------
__global__ void gather_edges(const int* __restrict__ offs,
                             const int* __restrict__ ecnt,
                             const int* __restrict__ esrc,
                             const __half* __restrict__ h,
                             const float* __restrict__ dinv,
                             const float* __restrict__ bias,
                             __half* __restrict__ o) {
    int warp = (blockIdx.x * blockDim.x + threadIdx.x) >> 5;
    int lane = threadIdx.x & 31;
    if (warp >= NN) return;
    int base = offs[warp];
    int end  = base + ecnt[warp];
    float di = dinv[warp];
    float di2 = di * di;
    float4 acc = reinterpret_cast<const float4*>(bias)[lane];
    {   // self contribution
        uint2 raw = reinterpret_cast<const uint2*>(h + (size_t)warp * HID)[lane];
        float2 f0 = __half22float2(*reinterpret_cast<__half2*>(&raw.x));
        float2 f1 = __half22float2(*reinterpret_cast<__half2*>(&raw.y));
        acc.x += f0.x * di2; acc.y += f0.y * di2;
        acc.z += f1.x * di2; acc.w += f1.y * di2;
    }
    for (int j0 = base; j0 < end; j0 += 32) {
        int e = j0 + lane;
        bool ok = e < end;
        int   s_l = ok ? esrc[e] : 0;
        float w_l = ok ? dinv[s_l] * di : 0.f;
        int m = min(32, end - j0);
        #pragma unroll 8
        for (int k = 0; k < m; k++) {
            int   ss = __shfl_sync(0xffffffffu, s_l, k);
            float ww = __shfl_sync(0xffffffffu, w_l, k);
            uint2 raw = reinterpret_cast<const uint2*>(h + (size_t)ss * HID)[lane];
            float2 f0 = __half22float2(*reinterpret_cast<__half2*>(&raw.x));
            float2 f1 = __half22float2(*reinterpret_cast<__half2*>(&raw.y));
            acc.x += f0.x * ww; acc.y += f0.y * ww;
            acc.z += f1.x * ww; acc.w += f1.y * ww;
        }
    }
    uint2 outp;
    *reinterpret_cast<__half2*>(&outp.x) = __floats2half2_rn(acc.x, acc.y);
    *reinterpret_cast<__half2*>(&outp.y) = __floats2half2_rn(acc.z, acc.w);
    reinterpret_cast<uint2*>(o + (size_t)warp * HID)[lane] = outp;
}

// ---------------- pipelined tf32 tensor-core GEMM ----------------------------
// A may be fp32 or fp16 (A_HALF); converted exactly to fp32 at fragment load,
// fed to tf32 MMA. B always fp32. Output fp32 (+bias) or fp16.
__device__ __forceinline__ void mma_tf32(float c[4], uint32_t a0, uint32_t a1,
                                         uint32_t a2, uint32_t a3,
                                         uint32_t b0, uint32_t b1) {
    asm volatile(
        "mma.sync.aligned.m16n8k8.row.col.f32.tf32.tf32.f32 "
        "{%0,%1,%2,%3}, {%4,%5,%6,%7}, {%8,%9}, {%0,%1,%2,%3};"
        : "+f"(c[0]), "+f"(c[1]), "+f"(c[2]), "+f"(c[3])
        : "r"(a0), "r"(a1), "r"(a2), "r"(a3), "r"(b0), "r"(b1));
}
__device__ __forceinline__ void cpasync16(uint32_t dst, const void* src, int sz) {
    asm volatile("cp.async.cg.shared.global [%0], [%1], 16, %2;"
                 :: "r"(dst), "l"(src), "r"(sz));
}
__device__ __forceinline__ void cp_commit() { asm volatile("cp.async.commit_group;"); }
__device__ __forceinline__ void cp_wait0()  { asm volatile("cp.async.wait_group 0;"); }

#define APAD_F 36                 // fp32 A row pad (words)
#define APAD_H 40                 // fp16 A row pad (halves); 80B rows, 16B-mult
#define A_BYTES(AH) ((AH) ? (2 * 128 * APAD_H * 2) : (2 * 128 * APAD_F * 4))
#define BPAD(BN) ((BN) + 8)
#define B_BYTES(BN) (2 * 32 * BPAD(BN) * 4)
#define GEMM_SMEM(AH, BN) (A_BYTES(AH) + B_BYTES(BN))

template<bool RELU_A, bool BIAS, bool OUT_HALF, bool A_HALF, int BN>
__global__ __launch_bounds__(256)
void tf32gemm(const void* __restrict__ Av,
              const float* __restrict__ B,
              void* __restrict__ Cv,
              const float* __restrict__ bias,
              int M, int N, int K, int ldb) {
    const int BM = 128, BK = 32;
    const int NT = BN / 16;
    extern __shared__ __align__(16) uint32_t smem[];
    // A tile views
    uint32_t (*Asf)[BM][APAD_F] = reinterpret_cast<uint32_t (*)[BM][APAD_F]>(smem);
    __half   (*Ash)[BM][APAD_H] = reinterpret_cast<__half (*)[BM][APAD_H]>(smem);
    uint32_t (*Bs)[BK][BPAD(BN)] =
        reinterpret_cast<uint32_t (*)[BK][BPAD(BN)]>(smem + A_BYTES(A_HALF) / 4);

    int tid  = threadIdx.x;
    int lane = tid & 31;
    int wid  = tid >> 5;
    int gid  = lane >> 2;
    int tig  = lane & 3;
    int wm   = (wid & 3) * 32;
    int wn   = (wid >> 2) * (BN / 2);

    int row0 = blockIdx.y * BM;
    int col0 = blockIdx.x * BN;

    uint32_t sA = (uint32_t)__cvta_generic_to_shared(&smem[0]);
    uint32_t sB = (uint32_t)__cvta_generic_to_shared(&Bs[0][0][0]);

    float acc[2][NT][4];
    #pragma unroll
    for (int mt = 0; mt < 2; mt++)
        #pragma unroll
        for (int nt = 0; nt < NT; nt++)
            #pragma unroll
            for (int r = 0; r < 4; r++) acc[mt][nt][r] = 0.f;

    int bRow = tid / (BN / 4);
    int bC4  = (tid % (BN / 4)) * 4;
    const int BROWSTEP = 256 / (BN / 4);

    auto loadA = [&](int k0, int st) {
        if (A_HALF) {
            const __half* A = (const __half*)Av;
            int aRow = tid >> 2;              // 4 chunks of 16B (8 halves) per row
            int aC8  = (tid & 3) * 8;
            #pragma unroll
            for (int i = 0; i < 2; i++) {
                int row = aRow + i * 64;
                int gr  = row0 + row;
                int grc = gr < M ? gr : M - 1;
                const __half* src = A + (size_t)grc * K + k0 + aC8;
                uint32_t dst = sA + ((st * BM + row) * APAD_H + aC8) * 2;
                cpasync16(dst, src, gr < M ? 16 : 0);
            }
        } else {
            const float* A = (const float*)Av;
            int aRow = tid >> 3;
            int aC4  = (tid & 7) * 4;
            #pragma unroll
            for (int i = 0; i < 4; i++) {
                int row = aRow + i * 32;
                int gr  = row0 + row;
                int grc = gr < M ? gr : M - 1;
                const float* src = A + (size_t)grc * K + k0 + aC4;
                uint32_t dst = sA + ((st * BM + row) * APAD_F + aC4) * 4;
                cpasync16(dst, src, gr < M ? 16 : 0);
            }
        }
    };
    auto loadB = [&](int k0, int st) {
        #pragma unroll
        for (int i = 0; i < 32 / BROWSTEP; i++) {
            int row = bRow + i * BROWSTEP;
            int gk  = k0 + row;
            int gc  = col0 + bC4;
            int rem = N - gc;
            int sz  = rem >= 4 ? 16 : (rem > 0 ? rem * 4 : 0);
            const float* src = B + (size_t)gk * ldb + (rem > 0 ? gc : 0);
            uint32_t dst = sB + (((st * BK + row) * BPAD(BN)) + bC4) * 4;
            cpasync16(dst, src, sz);
        }
    };

    // fragment fetch with optional half conversion + relu
    auto fragA = [&](int st, int r, int k) -> uint32_t {
        float v;
        if (A_HALF) v = __half2float(Ash[st][r][k]);
        else        v = __uint_as_float(Asf[st][r][k]);
        if (RELU_A) v = fmaxf(v, 0.f);
        return __float_as_uint(v);
    };

    int KT = K / BK;
    loadA(0, 0); loadB(0, 0);
    cp_commit();

    for (int kt = 0; kt < KT; kt++) {
        cp_wait0();
        __syncthreads();
        if (kt + 1 < KT) {
            loadA((kt + 1) * BK, (kt + 1) & 1);
            loadB((kt + 1) * BK, (kt + 1) & 1);
            cp_commit();
        }
        int st = kt & 1;
        #pragma unroll
        for (int kc = 0; kc < 4; kc++) {
            int ks = kc * 8;
            uint32_t a[2][4];
            #pragma unroll
            for (int mt = 0; mt < 2; mt++) {
                int r = wm + mt * 16 + gid;
                a[mt][0] = fragA(st, r,     ks + tig);
                a[mt][1] = fragA(st, r + 8, ks + tig);
                a[mt][2] = fragA(st, r,     ks + tig + 4);
                a[mt][3] = fragA(st, r + 8, ks + tig + 4);
            }
            uint32_t b[NT][2];
            #pragma unroll
            for (int nt = 0; nt < NT; nt++) {
                int c = wn + nt * 8 + gid;
                b[nt][0] = Bs[st][ks + tig    ][c];
                b[nt][1] = Bs[st][ks + tig + 4][c];
            }
            #pragma unroll
            for (int mt = 0; mt < 2; mt++)
                #pragma unroll
                for (int nt = 0; nt < NT; nt++)
                    mma_tf32(acc[mt][nt], a[mt][0], a[mt][1], a[mt][2], a[mt][3],
                             b[nt][0], b[nt][1]);
        }
        __syncthreads();
    }

    #pragma unroll
    for (int mt = 0; mt < 2; mt++) {
        #pragma unroll
        for (int rr = 0; rr < 2; rr++) {
            int gr = row0 + wm + mt * 16 + gid + rr * 8;
            if (gr >= M) continue;
            #pragma unroll
            for (int nt = 0; nt < NT; nt++) {
                int gc = col0 + wn + nt * 8 + tig * 2;
                float v0 = acc[mt][nt][rr * 2 + 0];
                float v1 = acc[mt][nt][rr * 2 + 1];
                if (OUT_HALF) {
                    __half* Ch = (__half*)Cv;
                    *reinterpret_cast<__half2*>(Ch + (size_t)gr * N + gc) =
                        __floats2half2_rn(v0, v1);
                } else {
                    float* Cf = (float*)Cv;
                    if (gc + 1 < N) {
                        float* cp = Cf + (size_t)gr * N + gc;
                        if (BIAS) {
                            *reinterpret_cast<float2*>(cp) =
                                make_float2(v0 + bias[gc], v1 + bias[gc + 1]);
                        } else {
                            *reinterpret_cast<float2*>(cp) = make_float2(v0, v1);
                        }
                    } else if (gc < N) {
                        Cf[(size_t)gr * N + gc] = BIAS ? v0 + bias[gc] : v0;
                    }
                }
            }
        }
    }
}

// ---------------- launch ------------------------------------------------------
extern "C" void kernel_launch(void* const* d_in, const int* in_sizes, int n_in,
                              void* d_out, int out_size) {
    const float* x    = (const float*)d_in[0];
    const int*   ei   = (const int*)d_in[1];
    const float* text = (const float*)d_in[2];
    const float* W1   = (const float*)d_in[3];
    const float* b1   = (const float*)d_in[4];
    const float* W2   = (const float*)d_in[5];
    const float* b2   = (const float*)d_in[6];
    const float* Wc   = (const float*)d_in[7];
    const float* bc   = (const float*)d_in[8];
    float* out = (float*)d_out;

    float *deg, *tv;
    __half *h1, *o1, *h2, *o2;
    int *ecnt, *offs, *cursor, *esrc, *counter;
    cudaGetSymbolAddress((void**)&deg,    g_deg);
    cudaGetSymbolAddress((void**)&h1,     g_h1);
    cudaGetSymbolAddress((void**)&o1,     g_o1);
    cudaGetSymbolAddress((void**)&h2,     g_h2);
    cudaGetSymbolAddress((void**)&o2,     g_o2);
    cudaGetSymbolAddress((void**)&tv,     g_tvec);
    cudaGetSymbolAddress((void**)&ecnt,   g_ecnt);
    cudaGetSymbolAddress((void**)&offs,   g_offs);
    cudaGetSymbolAddress((void**)&cursor, g_cursor);
    cudaGetSymbolAddress((void**)&esrc,   g_esrc);
    cudaGetSymbolAddress((void**)&counter,g_counter);

    cudaFuncSetAttribute(tf32gemm<false, false, true, false, 64>,
                         cudaFuncAttributeMaxDynamicSharedMemorySize,
                         GEMM_SMEM(false, 64));
    cudaFuncSetAttribute(tf32gemm<true, false, true, true, 64>,
                         cudaFuncAttributeMaxDynamicSharedMemorySize,
                         GEMM_SMEM(true, 64));
    cudaFuncSetAttribute(tf32gemm<false, true, false, true, 128>,
                         cudaFuncAttributeMaxDynamicSharedMemorySize,
                         GEMM_SMEM(true, 128));

    const int* srcp = ei;
    const int* dstp = ei + NE;

    // fork: prep chain on side stream, GEMM1 on main stream
    cudaStream_t s2;
    cudaStreamCreateWithFlags(&s2, cudaStreamNonBlocking);
    cudaEvent_t eFork, eCSR, eTxt;
    cudaEventCreateWithFlags(&eFork, cudaEventDisableTiming);
    cudaEventCreateWithFlags(&eCSR,  cudaEventDisableTiming);
    cudaEventCreateWithFlags(&eTxt,  cudaEventDisableTiming);

    cudaEventRecord(eFork, 0);
    cudaStreamWaitEvent(s2, eFork, 0);

    init_all   <<<(NN + 255) / 256, 256, 0, s2>>>(deg, tv, bc, counter);
    deg_count  <<<(NE + 255) / 256, 256, 0, s2>>>(dstp, deg);
    rsqrt_alloc<<<(NN + 255) / 256, 256, 0, s2>>>(deg, ecnt, offs, cursor, counter);
    fill_edges <<<(NE + 255) / 256, 256, 0, s2>>>(srcp, dstp, cursor, esrc);
    cudaEventRecord(eCSR, s2);
    dim3 gtp((OUTC + 127) / 128, TDIM / 128);
    text_proj_part<<<gtp, 128, 0, s2>>>(text, Wc, tv);
    cudaEventRecord(eTxt, s2);

    dim3 gHid(2, (NN + 127) / 128);
    dim3 gOut((OUTC + 127) / 128, (NN + 127) / 128);
    int gatherBlocks = (NN * 32 + 255) / 256;

    // main: GEMM1 (A fp32, out fp16)
    tf32gemm<false, false, true, false, 64><<<gHid, 256, GEMM_SMEM(false, 64)>>>(
        x, W1, h1, nullptr, NN, HID, INC, HID);

    // join CSR, gather1 -> o1 fp16
    cudaStreamWaitEvent(0, eCSR, 0);
    gather_edges<<<gatherBlocks, 256>>>(offs, ecnt, esrc, h1, deg, b1, o1);

    // layer 2: A = o1 fp16 (relu in fragment load), out h2 fp16
    tf32gemm<true, false, true, true, 64><<<gHid, 256, GEMM_SMEM(true, 64)>>>(
        o1, W2, h2, nullptr, NN, HID, HID, HID);
    gather_edges<<<gatherBlocks, 256>>>(offs, ecnt, esrc, h2, deg, b2, o2);

    // classifier: A = o2 fp16, out fp32 + tvec
    cudaStreamWaitEvent(0, eTxt, 0);
    tf32gemm<false, true, false, true, 128><<<gOut, 256, GEMM_SMEM(true, 128)>>>(
        o2, Wc, out, tv, NN, OUTC, HID, OUTC);
}